// round 6
// baseline (speedup 1.0000x reference)
#include <cuda_runtime.h>
#include <cstdint>

#define BB   32
#define TT   128
#define KD   32
#define HH   4
#define DINP 160
#define HIDN 256

// Scratch (static device globals; no allocation).
__device__ float g_qT[BB * HH * KD * TT];   // [b][h][kk][i]  2MB
__device__ float g_kT[BB * HH * KD * TT];   // [b][h][kk][j]
__device__ float g_vT[BB * HH * KD * TT];   // [b][h][d][j]
__device__ float g_act[BB * TT * DINP];     // [x | state]  4096 x 160

typedef unsigned long long ull;

__device__ __forceinline__ ull ffma2(ull a, ull b, ull c) {
    ull d;
    asm("fma.rn.f32x2 %0, %1, %2, %3;" : "=l"(d) : "l"(a), "l"(b), "l"(c));
    return d;
}
__device__ __forceinline__ ull pack2(float x, float y) {
    ull r;
    asm("mov.b64 %0, {%1, %2};" : "=l"(r) : "f"(x), "f"(y));
    return r;
}
__device__ __forceinline__ float2 unpack2(ull v) {
    float x, y;
    asm("mov.b64 {%0, %1}, %2;" : "=f"(x), "=f"(y) : "l"(v));
    return make_float2(x, y);
}
__device__ __forceinline__ void cpa16(uint32_t dst_smem, const void* src) {
    asm volatile("cp.async.cg.shared.global [%0], [%1], 16;\n"
                 :: "r"(dst_smem), "l"(src) : "memory");
}
__device__ __forceinline__ void cpa_commit() {
    asm volatile("cp.async.commit_group;\n" ::: "memory");
}
template <int N>
__device__ __forceinline__ void cpa_wait() {
    asm volatile("cp.async.wait_group %0;\n" :: "n"(N) : "memory");
}

// ---------------------------------------------------------------------------
// Kernel 0: projections with transposed output + state tail copy into g_act.
// grid 384: blockIdx = rb (128 row-blocks of 32) + mat*128.
// ---------------------------------------------------------------------------
__global__ void __launch_bounds__(256) proj_kernel(
    const float* __restrict__ state,
    const float* __restrict__ Wq,
    const float* __restrict__ Wk,
    const float* __restrict__ Wv)
{
    __shared__ float sT[KD][36];       // stateT tile [c][r]
    __shared__ float Ws[KD * 128];     // W rows [k][c]

    const int bx  = blockIdx.x;
    const int rb  = bx & 127;
    const int mat = bx >> 7;
    const float* W = (mat == 0) ? Wq : (mat == 1) ? Wk : Wv;
    float* dstBase = (mat == 0) ? g_qT : (mat == 1) ? g_kT : g_vT;
    const int row0 = rb * 32;
    const int t = threadIdx.x;

    {   // stage W (32x128)
        const float4* src = (const float4*)W;
        float4* dst = (float4*)Ws;
        #pragma unroll
        for (int n = t; n < KD * 128 / 4; n += 256) dst[n] = src[n];
    }
    {   // stage state tile transposed; mat-0 blocks also copy the concat tail
        int r = t >> 3, c0 = (t & 7) * 4;
        float4 v = *(const float4*)(state + (size_t)(row0 + r) * KD + c0);
        sT[c0 + 0][r] = v.x; sT[c0 + 1][r] = v.y;
        sT[c0 + 2][r] = v.z; sT[c0 + 3][r] = v.w;
        if (mat == 0)
            *(float4*)(g_act + (size_t)(row0 + r) * DINP + 4 * KD + c0) = v;
    }
    __syncthreads();

    const int rg = t >> 5, cg = t & 31;
    const int r0 = rg * 4, c0 = cg * 4;
    ull acc[4][2];
    #pragma unroll
    for (int r = 0; r < 4; r++) { acc[r][0] = 0ull; acc[r][1] = 0ull; }

    #pragma unroll 8
    for (int k = 0; k < KD; k++) {
        float4 a4 = *(const float4*)&sT[k][r0];
        ulonglong2 b2 = *(const ulonglong2*)(Ws + k * 128 + c0);
        ull ad;
        ad = pack2(a4.x, a4.x); acc[0][0] = ffma2(ad, b2.x, acc[0][0]); acc[0][1] = ffma2(ad, b2.y, acc[0][1]);
        ad = pack2(a4.y, a4.y); acc[1][0] = ffma2(ad, b2.x, acc[1][0]); acc[1][1] = ffma2(ad, b2.y, acc[1][1]);
        ad = pack2(a4.z, a4.z); acc[2][0] = ffma2(ad, b2.x, acc[2][0]); acc[2][1] = ffma2(ad, b2.y, acc[2][1]);
        ad = pack2(a4.w, a4.w); acc[3][0] = ffma2(ad, b2.x, acc[3][0]); acc[3][1] = ffma2(ad, b2.y, acc[3][1]);
    }

    // transposed store
    const int b  = row0 >> 7;
    const int i0 = (row0 & 127) + r0;
    float cs[4][4];
    #pragma unroll
    for (int r = 0; r < 4; r++) {
        float2 p0 = unpack2(acc[r][0]), p1 = unpack2(acc[r][1]);
        cs[r][0] = p0.x; cs[r][1] = p0.y; cs[r][2] = p1.x; cs[r][3] = p1.y;
    }
    #pragma unroll
    for (int cc = 0; cc < 4; cc++) {
        int c = c0 + cc;
        int h = c >> 5, kk = c & 31;
        float4 o = make_float4(cs[0][cc], cs[1][cc], cs[2][cc], cs[3][cc]);
        *(float4*)(dstBase + ((size_t)((b * HH + h) * KD + kk)) * TT + i0) = o;
    }
}

// ---------------------------------------------------------------------------
// Kernel 1: masked attention for 64 query rows of one (b,h).
// grid 256 = (b, h, ihalf). Scores transposed in smem P[j][i].
// ---------------------------------------------------------------------------
__global__ void __launch_bounds__(256, 2) attn_kernel()
{
    __shared__ float P[TT * 64];       // [j][i]  32KB
    __shared__ float s_mx[4][64];
    __shared__ float s_sm[4][64];
    __shared__ float s_inv[64];

    const int bx = blockIdx.x;
    const int b = bx >> 3, h = (bx >> 1) & 3, ihalf = bx & 1;
    const int t = threadIdx.x;
    const int ig0 = ihalf * 64;
    const float* QT = g_qT + (size_t)((b * HH + h) * KD) * TT;
    const float* KT = g_kT + (size_t)((b * HH + h) * KD) * TT;
    const float* VT = g_vT + (size_t)((b * HH + h) * KD) * TT;

    // ---- GEMM1: S^T[j][i] = K[j]·Q[i]; tile 8i x 4j
    {
        const int ig = t >> 5, jg = t & 31;
        const int i0 = ig * 8, j0 = jg * 4;
        ull acc[4][4];
        #pragma unroll
        for (int c = 0; c < 4; c++)
            #pragma unroll
            for (int p = 0; p < 4; p++) acc[c][p] = 0ull;

        #pragma unroll 4
        for (int kk = 0; kk < KD; kk++) {
            const float* qrow = QT + kk * TT + ig0 + i0;
            ulonglong2 a01 = *(const ulonglong2*)qrow;
            ulonglong2 a23 = *(const ulonglong2*)(qrow + 4);
            float4 bj = *(const float4*)(KT + kk * TT + j0);
            ull bd;
            bd = pack2(bj.x, bj.x);
            acc[0][0] = ffma2(bd, a01.x, acc[0][0]); acc[0][1] = ffma2(bd, a01.y, acc[0][1]);
            acc[0][2] = ffma2(bd, a23.x, acc[0][2]); acc[0][3] = ffma2(bd, a23.y, acc[0][3]);
            bd = pack2(bj.y, bj.y);
            acc[1][0] = ffma2(bd, a01.x, acc[1][0]); acc[1][1] = ffma2(bd, a01.y, acc[1][1]);
            acc[1][2] = ffma2(bd, a23.x, acc[1][2]); acc[1][3] = ffma2(bd, a23.y, acc[1][3]);
            bd = pack2(bj.z, bj.z);
            acc[2][0] = ffma2(bd, a01.x, acc[2][0]); acc[2][1] = ffma2(bd, a01.y, acc[2][1]);
            acc[2][2] = ffma2(bd, a23.x, acc[2][2]); acc[2][3] = ffma2(bd, a23.y, acc[2][3]);
            bd = pack2(bj.w, bj.w);
            acc[3][0] = ffma2(bd, a01.x, acc[3][0]); acc[3][1] = ffma2(bd, a01.y, acc[3][1]);
            acc[3][2] = ffma2(bd, a23.x, acc[3][2]); acc[3][3] = ffma2(bd, a23.y, acc[3][3]);
        }

        #pragma unroll
        for (int c = 0; c < 4; c++) {
            int jglob = j0 + c;
            int rd = jglob - ig0 - i0;          // diag position within my 8 i's
            if (rd >= 0 && rd < 8) {
                int p = rd >> 1, hi = rd & 1;
                float2 v = unpack2(acc[c][p]);
                if (hi) v.y = -1e30f; else v.x = -1e30f;
                acc[c][p] = pack2(v.x, v.y);
            }
            ull* dst = (ull*)&P[jglob * 64 + i0];
            dst[0] = acc[c][0]; dst[1] = acc[c][1];
            dst[2] = acc[c][2]; dst[3] = acc[c][3];
        }
    }
    __syncthreads();

    // ---- softmax (over j) on P, in place
    {
        const float scale = 0.17677669529663687f;   // 1/sqrt(32)
        const int i = t & 63, q = t >> 6;
        float mx = -1e30f;
        #pragma unroll 8
        for (int jj = 0; jj < 32; jj++)
            mx = fmaxf(mx, P[(q * 32 + jj) * 64 + i]);
        s_mx[q][i] = mx;
        __syncthreads();
        float m = fmaxf(fmaxf(s_mx[0][i], s_mx[1][i]), fmaxf(s_mx[2][i], s_mx[3][i]));
        float sum = 0.f;
        #pragma unroll 8
        for (int jj = 0; jj < 32; jj++) {
            int idx = (q * 32 + jj) * 64 + i;
            float e = __expf((P[idx] - m) * scale);
            P[idx] = e;
            sum += e;
        }
        s_sm[q][i] = sum;
    }
    __syncthreads();
    if (t < 64)
        s_inv[t] = 1.f / (s_sm[0][t] + s_sm[1][t] + s_sm[2][t] + s_sm[3][t]);
    __syncthreads();

    // ---- GEMM2: O[i][d] = sum_j P[j][i] * V[j][d]; tile 4i x 2d,
    //      j chunked by 4 so V comes in as LDG.128 along contiguous j.
    {
        const int ig = t & 15, dg = t >> 4;
        const int i0 = ig * 4, d0 = dg * 2;
        ull o[2][2];
        o[0][0] = 0ull; o[0][1] = 0ull; o[1][0] = 0ull; o[1][1] = 0ull;
        const float* v0p = VT + (size_t)d0 * TT;
        const float* v1p = v0p + TT;

        for (int j = 0; j < TT; j += 4) {
            float4 v40 = *(const float4*)(v0p + j);
            float4 v41 = *(const float4*)(v1p + j);
            float va0[4] = {v40.x, v40.y, v40.z, v40.w};
            float va1[4] = {v41.x, v41.y, v41.z, v41.w};
            #pragma unroll
            for (int u = 0; u < 4; u++) {
                ulonglong2 a = *(const ulonglong2*)&P[(j + u) * 64 + i0];
                ull vd0 = pack2(va0[u], va0[u]);
                ull vd1 = pack2(va1[u], va1[u]);
                o[0][0] = ffma2(vd0, a.x, o[0][0]); o[0][1] = ffma2(vd0, a.y, o[0][1]);
                o[1][0] = ffma2(vd1, a.x, o[1][0]); o[1][1] = ffma2(vd1, a.y, o[1][1]);
            }
        }

        #pragma unroll
        for (int p = 0; p < 2; p++) {
            float2 e0 = unpack2(o[0][p]);
            float2 e1 = unpack2(o[1][p]);
            float r0[2] = {e0.x, e0.y};
            float r1[2] = {e1.x, e1.y};
            #pragma unroll
            for (int u = 0; u < 2; u++) {
                int il = i0 + p * 2 + u;
                int iglob = ig0 + il;
                float inv = s_inv[il];
                float out0 = r0[u] * inv - v0p[iglob];
                float out1 = r1[u] * inv - v1p[iglob];
                *(float2*)(g_act + ((size_t)b * TT + iglob) * DINP + h * KD + d0)
                    = make_float2(out0, out1);
            }
        }
    }
}

// ---------------------------------------------------------------------------
// Kernel 2 (fused MLP): h1 = relu(act@W1+b1); h2 = relu(h1@W2+b2);
// out = h2@Wo + bo. 16 rows/block, 256 threads (8 warps), grid 256.
// Thread tile 2 rows x 8 cols; h1 lives only in smem; W panels (8 k-rows)
// cp.async double-buffered.
// ---------------------------------------------------------------------------
#define CKP 8
__global__ void __launch_bounds__(256) mlp_kernel(
    const float* __restrict__ W1, const float* __restrict__ b1,
    const float* __restrict__ W2, const float* __restrict__ b2,
    const float* __restrict__ Wo, const float* __restrict__ bo,
    float* __restrict__ out)
{
    __shared__ float s_a[16 * DINP];           // [row][k]  10KB
    __shared__ float s_h1[16 * HIDN];          // [row][k]  16KB
    __shared__ float s_w[2][CKP * HIDN];       // 2 x 8KB

    const int rbase = blockIdx.x * 16;
    const int t = threadIdx.x;
    const int c0 = (t & 31) * 8;
    const int r0 = (t >> 5) * 2;               // warp w -> rows 2w, 2w+1
    const uint32_t wsm = (uint32_t)__cvta_generic_to_shared(&s_w[0][0]);

    // prologue: W1 panel 0 -> buf 0 (async), act tile -> smem (sync loads)
    #pragma unroll
    for (int u = 0; u < 2; u++)
        cpa16(wsm + (uint32_t)(t + u * 256) * 16, W1 + (size_t)(t + u * 256) * 4);
    cpa_commit();
    {
        const float4* src = (const float4*)(g_act + (size_t)rbase * DINP);
        float4* dst = (float4*)s_a;
        #pragma unroll
        for (int n = t; n < 16 * DINP / 4; n += 256) dst[n] = src[n];
    }

    ull acc[2][4];
    {
        float4 bl = *(const float4*)(b1 + c0);
        float4 bh = *(const float4*)(b1 + c0 + 4);
        #pragma unroll
        for (int r = 0; r < 2; r++) {
            acc[r][0] = pack2(bl.x, bl.y); acc[r][1] = pack2(bl.z, bl.w);
            acc[r][2] = pack2(bh.x, bh.y); acc[r][3] = pack2(bh.z, bh.w);
        }
    }

    // ---- phase 1: k = 0..159 over W1
    const int NCH1 = DINP / CKP;   // 20
    for (int ch = 0; ch < NCH1; ch++) {
        if (ch + 1 < NCH1) {
            const uint32_t dstb = wsm + (uint32_t)(((ch + 1) & 1) * CKP * HIDN) * 4;
            const float* srcb = W1 + (size_t)(ch + 1) * CKP * HIDN;
            #pragma unroll
            for (int u = 0; u < 2; u++)
                cpa16(dstb + (uint32_t)(t + u * 256) * 16, srcb + (size_t)(t + u * 256) * 4);
            cpa_commit();
            cpa_wait<1>();
        } else {
            cpa_wait<0>();
        }
        __syncthreads();
        const float* wp = &s_w[ch & 1][0];
        const int kg0 = ch * CKP;
        #pragma unroll
        for (int kk = 0; kk < CKP; kk++) {
            ulonglong2 w01 = *(const ulonglong2*)(wp + kk * HIDN + c0);
            ulonglong2 w23 = *(const ulonglong2*)(wp + kk * HIDN + c0 + 4);
            float a0 = s_a[(r0 + 0) * DINP + kg0 + kk];
            float a1 = s_a[(r0 + 1) * DINP + kg0 + kk];
            ull ad;
            ad = pack2(a0, a0);
            acc[0][0] = ffma2(ad, w01.x, acc[0][0]); acc[0][1] = ffma2(ad, w01.y, acc[0][1]);
            acc[0][2] = ffma2(ad, w23.x, acc[0][2]); acc[0][3] = ffma2(ad, w23.y, acc[0][3]);
            ad = pack2(a1, a1);
            acc[1][0] = ffma2(ad, w01.x, acc[1][0]); acc[1][1] = ffma2(ad, w01.y, acc[1][1]);
            acc[1][2] = ffma2(ad, w23.x, acc[1][2]); acc[1][3] = ffma2(ad, w23.y, acc[1][3]);
        }
        __syncthreads();
    }

    // ---- relu -> s_h1 (STS.128), prefetch W2 panel 0
    #pragma unroll
    for (int u = 0; u < 2; u++)
        cpa16(wsm + (uint32_t)(t + u * 256) * 16, W2 + (size_t)(t + u * 256) * 4);
    cpa_commit();
    #pragma unroll
    for (int r = 0; r < 2; r++) {
        float2 p0 = unpack2(acc[r][0]), p1 = unpack2(acc[r][1]);
        float2 p2 = unpack2(acc[r][2]), p3 = unpack2(acc[r][3]);
        float* hrow = s_h1 + (r0 + r) * HIDN + c0;
        *(float4*)hrow = make_float4(fmaxf(p0.x, 0.f), fmaxf(p0.y, 0.f),
                                     fmaxf(p1.x, 0.f), fmaxf(p1.y, 0.f));
        *(float4*)(hrow + 4) = make_float4(fmaxf(p2.x, 0.f), fmaxf(p2.y, 0.f),
                                           fmaxf(p3.x, 0.f), fmaxf(p3.y, 0.f));
    }
    {
        float4 bl = *(const float4*)(b2 + c0);
        float4 bh = *(const float4*)(b2 + c0 + 4);
        #pragma unroll
        for (int r = 0; r < 2; r++) {
            acc[r][0] = pack2(bl.x, bl.y); acc[r][1] = pack2(bl.z, bl.w);
            acc[r][2] = pack2(bh.x, bh.y); acc[r][3] = pack2(bh.z, bh.w);
        }
    }
    __syncthreads();

    // ---- phase 2: k = 0..255 over W2, reading s_h1
    const int NCH2 = HIDN / CKP;   // 32
    for (int ch = 0; ch < NCH2; ch++) {
        if (ch + 1 < NCH2) {
            const uint32_t dstb = wsm + (uint32_t)(((ch + 1) & 1) * CKP * HIDN) * 4;
            const float* srcb = W2 + (size_t)(ch + 1) * CKP * HIDN;
            #pragma unroll
            for (int u = 0; u < 2; u++)
                cpa16(dstb + (uint32_t)(t + u * 256) * 16, srcb + (size_t)(t + u * 256) * 4);
            cpa_commit();
            cpa_wait<1>();
        } else {
            cpa_wait<0>();
        }
        __syncthreads();
        const float* wp = &s_w[ch & 1][0];
        const int kg0 = ch * CKP;
        #pragma unroll
        for (int kk = 0; kk < CKP; kk++) {
            ulonglong2 w01 = *(const ulonglong2*)(wp + kk * HIDN + c0);
            ulonglong2 w23 = *(const ulonglong2*)(wp + kk * HIDN + c0 + 4);
            float a0 = s_h1[(r0 + 0) * HIDN + kg0 + kk];
            float a1 = s_h1[(r0 + 1) * HIDN + kg0 + kk];
            ull ad;
            ad = pack2(a0, a0);
            acc[0][0] = ffma2(ad, w01.x, acc[0][0]); acc[0][1] = ffma2(ad, w01.y, acc[0][1]);
            acc[0][2] = ffma2(ad, w23.x, acc[0][2]); acc[0][3] = ffma2(ad, w23.y, acc[0][3]);
            ad = pack2(a1, a1);
            acc[1][0] = ffma2(ad, w01.x, acc[1][0]); acc[1][1] = ffma2(ad, w01.y, acc[1][1]);
            acc[1][2] = ffma2(ad, w23.x, acc[1][2]); acc[1][3] = ffma2(ad, w23.y, acc[1][3]);
        }
        __syncthreads();
    }

    // ---- relu + dot with Wo slice; one warp spans all 256 cols -> pure shfl
    float4 wl = *(const float4*)(Wo + c0);
    float4 wh = *(const float4*)(Wo + c0 + 4);
    float p[2];
    #pragma unroll
    for (int r = 0; r < 2; r++) {
        float2 p0 = unpack2(acc[r][0]), p1 = unpack2(acc[r][1]);
        float2 p2 = unpack2(acc[r][2]), p3 = unpack2(acc[r][3]);
        float s = 0.f;
        s = fmaf(fmaxf(p0.x, 0.f), wl.x, s);
        s = fmaf(fmaxf(p0.y, 0.f), wl.y, s);
        s = fmaf(fmaxf(p1.x, 0.f), wl.z, s);
        s = fmaf(fmaxf(p1.y, 0.f), wl.w, s);
        s = fmaf(fmaxf(p2.x, 0.f), wh.x, s);
        s = fmaf(fmaxf(p2.y, 0.f), wh.y, s);
        s = fmaf(fmaxf(p3.x, 0.f), wh.z, s);
        s = fmaf(fmaxf(p3.y, 0.f), wh.w, s);
        p[r] = s;
    }
    #pragma unroll
    for (int off = 16; off; off >>= 1) {
        #pragma unroll
        for (int r = 0; r < 2; r++)
            p[r] += __shfl_down_sync(0xffffffffu, p[r], off);
    }
    if ((t & 31) == 0) {
        float bv = bo[0];
        #pragma unroll
        for (int r = 0; r < 2; r++)
            out[rbase + r0 + r] = p[r] + bv;
    }
}

// ---------------------------------------------------------------------------
extern "C" void kernel_launch(void* const* d_in, const int* in_sizes, int n_in,
                              void* d_out, int out_size)
{
    (void)in_sizes; (void)n_in; (void)out_size;
    const float* state = (const float*)d_in[0];
    const float* Wq    = (const float*)d_in[1];
    const float* Wk    = (const float*)d_in[2];
    const float* Wv    = (const float*)d_in[3];
    const float* W1    = (const float*)d_in[4];
    const float* b1    = (const float*)d_in[5];
    const float* W2    = (const float*)d_in[6];
    const float* b2    = (const float*)d_in[7];
    const float* Wo    = (const float*)d_in[8];
    const float* bo    = (const float*)d_in[9];
    float* out = (float*)d_out;

    proj_kernel<<<384, 256>>>(state, Wq, Wk, Wv);
    attn_kernel<<<BB * HH * 2, 256>>>();
    mlp_kernel<<<(BB * TT) / 16, 256>>>(W1, b1, W2, b2, Wo, bo, out);
}

// round 7
// speedup vs baseline: 1.2936x; 1.2936x over previous
#include <cuda_runtime.h>
#include <cstdint>

#define BB   32
#define TT   128
#define KD   32
#define HH   4
#define DINP 160
#define HIDN 256

// Scratch (static device globals; no allocation).
__device__ float g_qT[BB * HH * KD * TT];   // [b][h][kk][i]  2MB
__device__ float g_kT[BB * HH * KD * TT];   // [b][h][kk][j]
__device__ float g_vT[BB * HH * KD * TT];   // [b][h][d][j]
__device__ float g_act[BB * TT * DINP];     // [x | state]  4096 x 160

typedef unsigned long long ull;

__device__ __forceinline__ ull ffma2(ull a, ull b, ull c) {
    ull d;
    asm("fma.rn.f32x2 %0, %1, %2, %3;" : "=l"(d) : "l"(a), "l"(b), "l"(c));
    return d;
}
__device__ __forceinline__ ull pack2(float x, float y) {
    ull r;
    asm("mov.b64 %0, {%1, %2};" : "=l"(r) : "f"(x), "f"(y));
    return r;
}
__device__ __forceinline__ float2 unpack2(ull v) {
    float x, y;
    asm("mov.b64 {%0, %1}, %2;" : "=f"(x), "=f"(y) : "l"(v));
    return make_float2(x, y);
}
__device__ __forceinline__ void cpa16(uint32_t dst_smem, const void* src) {
    asm volatile("cp.async.cg.shared.global [%0], [%1], 16;\n"
                 :: "r"(dst_smem), "l"(src) : "memory");
}
__device__ __forceinline__ void cpa_commit() {
    asm volatile("cp.async.commit_group;\n" ::: "memory");
}
template <int N>
__device__ __forceinline__ void cpa_wait() {
    asm volatile("cp.async.wait_group %0;\n" :: "n"(N) : "memory");
}

// ---------------------------------------------------------------------------
// Kernel 0: projections with transposed output + state tail copy into g_act.
// grid 384: blockIdx = rb (128 row-blocks of 32) + mat*128.
// ---------------------------------------------------------------------------
__global__ void __launch_bounds__(256) proj_kernel(
    const float* __restrict__ state,
    const float* __restrict__ Wq,
    const float* __restrict__ Wk,
    const float* __restrict__ Wv)
{
    __shared__ float sT[KD][36];       // stateT tile [c][r]
    __shared__ float Ws[KD * 128];     // W rows [k][c]

    const int bx  = blockIdx.x;
    const int rb  = bx & 127;
    const int mat = bx >> 7;
    const float* W = (mat == 0) ? Wq : (mat == 1) ? Wk : Wv;
    float* dstBase = (mat == 0) ? g_qT : (mat == 1) ? g_kT : g_vT;
    const int row0 = rb * 32;
    const int t = threadIdx.x;

    {   // stage W (32x128)
        const float4* src = (const float4*)W;
        float4* dst = (float4*)Ws;
        #pragma unroll
        for (int n = t; n < KD * 128 / 4; n += 256) dst[n] = src[n];
    }
    {   // stage state tile transposed; mat-0 blocks also copy the concat tail
        int r = t >> 3, c0 = (t & 7) * 4;
        float4 v = *(const float4*)(state + (size_t)(row0 + r) * KD + c0);
        sT[c0 + 0][r] = v.x; sT[c0 + 1][r] = v.y;
        sT[c0 + 2][r] = v.z; sT[c0 + 3][r] = v.w;
        if (mat == 0)
            *(float4*)(g_act + (size_t)(row0 + r) * DINP + 4 * KD + c0) = v;
    }
    __syncthreads();

    const int rg = t >> 5, cg = t & 31;
    const int r0 = rg * 4, c0 = cg * 4;
    ull acc[4][2];
    #pragma unroll
    for (int r = 0; r < 4; r++) { acc[r][0] = 0ull; acc[r][1] = 0ull; }

    #pragma unroll 8
    for (int k = 0; k < KD; k++) {
        float4 a4 = *(const float4*)&sT[k][r0];
        ulonglong2 b2 = *(const ulonglong2*)(Ws + k * 128 + c0);
        ull ad;
        ad = pack2(a4.x, a4.x); acc[0][0] = ffma2(ad, b2.x, acc[0][0]); acc[0][1] = ffma2(ad, b2.y, acc[0][1]);
        ad = pack2(a4.y, a4.y); acc[1][0] = ffma2(ad, b2.x, acc[1][0]); acc[1][1] = ffma2(ad, b2.y, acc[1][1]);
        ad = pack2(a4.z, a4.z); acc[2][0] = ffma2(ad, b2.x, acc[2][0]); acc[2][1] = ffma2(ad, b2.y, acc[2][1]);
        ad = pack2(a4.w, a4.w); acc[3][0] = ffma2(ad, b2.x, acc[3][0]); acc[3][1] = ffma2(ad, b2.y, acc[3][1]);
    }

    // transposed store
    const int b  = row0 >> 7;
    const int i0 = (row0 & 127) + r0;
    float cs[4][4];
    #pragma unroll
    for (int r = 0; r < 4; r++) {
        float2 p0 = unpack2(acc[r][0]), p1 = unpack2(acc[r][1]);
        cs[r][0] = p0.x; cs[r][1] = p0.y; cs[r][2] = p1.x; cs[r][3] = p1.y;
    }
    #pragma unroll
    for (int cc = 0; cc < 4; cc++) {
        int c = c0 + cc;
        int h = c >> 5, kk = c & 31;
        float4 o = make_float4(cs[0][cc], cs[1][cc], cs[2][cc], cs[3][cc]);
        *(float4*)(dstBase + ((size_t)((b * HH + h) * KD + kk)) * TT + i0) = o;
    }
}

// ---------------------------------------------------------------------------
// Kernel 1: masked attention for 64 query rows of one (b,h).
// grid 256 = (b, h, ihalf). Scores transposed in smem P[j][i].
// ---------------------------------------------------------------------------
__global__ void __launch_bounds__(256, 2) attn_kernel()
{
    __shared__ float P[TT * 64];       // [j][i]  32KB
    __shared__ float s_mx[4][64];
    __shared__ float s_sm[4][64];
    __shared__ float s_inv[64];

    const int bx = blockIdx.x;
    const int b = bx >> 3, h = (bx >> 1) & 3, ihalf = bx & 1;
    const int t = threadIdx.x;
    const int ig0 = ihalf * 64;
    const float* QT = g_qT + (size_t)((b * HH + h) * KD) * TT;
    const float* KT = g_kT + (size_t)((b * HH + h) * KD) * TT;
    const float* VT = g_vT + (size_t)((b * HH + h) * KD) * TT;

    // ---- GEMM1: S^T[j][i] = K[j]·Q[i]; tile 8i x 4j
    {
        const int ig = t >> 5, jg = t & 31;
        const int i0 = ig * 8, j0 = jg * 4;
        ull acc[4][4];
        #pragma unroll
        for (int c = 0; c < 4; c++)
            #pragma unroll
            for (int p = 0; p < 4; p++) acc[c][p] = 0ull;

        #pragma unroll 4
        for (int kk = 0; kk < KD; kk++) {
            const float* qrow = QT + kk * TT + ig0 + i0;
            ulonglong2 a01 = *(const ulonglong2*)qrow;
            ulonglong2 a23 = *(const ulonglong2*)(qrow + 4);
            float4 bj = *(const float4*)(KT + kk * TT + j0);
            ull bd;
            bd = pack2(bj.x, bj.x);
            acc[0][0] = ffma2(bd, a01.x, acc[0][0]); acc[0][1] = ffma2(bd, a01.y, acc[0][1]);
            acc[0][2] = ffma2(bd, a23.x, acc[0][2]); acc[0][3] = ffma2(bd, a23.y, acc[0][3]);
            bd = pack2(bj.y, bj.y);
            acc[1][0] = ffma2(bd, a01.x, acc[1][0]); acc[1][1] = ffma2(bd, a01.y, acc[1][1]);
            acc[1][2] = ffma2(bd, a23.x, acc[1][2]); acc[1][3] = ffma2(bd, a23.y, acc[1][3]);
            bd = pack2(bj.z, bj.z);
            acc[2][0] = ffma2(bd, a01.x, acc[2][0]); acc[2][1] = ffma2(bd, a01.y, acc[2][1]);
            acc[2][2] = ffma2(bd, a23.x, acc[2][2]); acc[2][3] = ffma2(bd, a23.y, acc[2][3]);
            bd = pack2(bj.w, bj.w);
            acc[3][0] = ffma2(bd, a01.x, acc[3][0]); acc[3][1] = ffma2(bd, a01.y, acc[3][1]);
            acc[3][2] = ffma2(bd, a23.x, acc[3][2]); acc[3][3] = ffma2(bd, a23.y, acc[3][3]);
        }

        #pragma unroll
        for (int c = 0; c < 4; c++) {
            int jglob = j0 + c;
            int rd = jglob - ig0 - i0;          // diag position within my 8 i's
            if (rd >= 0 && rd < 8) {
                int p = rd >> 1, hi = rd & 1;
                float2 v = unpack2(acc[c][p]);
                if (hi) v.y = -1e30f; else v.x = -1e30f;
                acc[c][p] = pack2(v.x, v.y);
            }
            ull* dst = (ull*)&P[jglob * 64 + i0];
            dst[0] = acc[c][0]; dst[1] = acc[c][1];
            dst[2] = acc[c][2]; dst[3] = acc[c][3];
        }
    }
    __syncthreads();

    // ---- softmax (over j) on P, in place
    {
        const float scale = 0.17677669529663687f;   // 1/sqrt(32)
        const int i = t & 63, q = t >> 6;
        float mx = -1e30f;
        #pragma unroll 8
        for (int jj = 0; jj < 32; jj++)
            mx = fmaxf(mx, P[(q * 32 + jj) * 64 + i]);
        s_mx[q][i] = mx;
        __syncthreads();
        float m = fmaxf(fmaxf(s_mx[0][i], s_mx[1][i]), fmaxf(s_mx[2][i], s_mx[3][i]));
        float sum = 0.f;
        #pragma unroll 8
        for (int jj = 0; jj < 32; jj++) {
            int idx = (q * 32 + jj) * 64 + i;
            float e = __expf((P[idx] - m) * scale);
            P[idx] = e;
            sum += e;
        }
        s_sm[q][i] = sum;
    }
    __syncthreads();
    if (t < 64)
        s_inv[t] = 1.f / (s_sm[0][t] + s_sm[1][t] + s_sm[2][t] + s_sm[3][t]);
    __syncthreads();

    // ---- GEMM2: O[i][d] = sum_j P[j][i] * V[j][d]; tile 4i x 2d,
    //      j chunked by 4 so V comes in as LDG.128 along contiguous j.
    {
        const int ig = t & 15, dg = t >> 4;
        const int i0 = ig * 4, d0 = dg * 2;
        ull o[2][2];
        o[0][0] = 0ull; o[0][1] = 0ull; o[1][0] = 0ull; o[1][1] = 0ull;
        const float* v0p = VT + (size_t)d0 * TT;
        const float* v1p = v0p + TT;

        for (int j = 0; j < TT; j += 4) {
            float4 v40 = *(const float4*)(v0p + j);
            float4 v41 = *(const float4*)(v1p + j);
            float va0[4] = {v40.x, v40.y, v40.z, v40.w};
            float va1[4] = {v41.x, v41.y, v41.z, v41.w};
            #pragma unroll
            for (int u = 0; u < 4; u++) {
                ulonglong2 a = *(const ulonglong2*)&P[(j + u) * 64 + i0];
                ull vd0 = pack2(va0[u], va0[u]);
                ull vd1 = pack2(va1[u], va1[u]);
                o[0][0] = ffma2(vd0, a.x, o[0][0]); o[0][1] = ffma2(vd0, a.y, o[0][1]);
                o[1][0] = ffma2(vd1, a.x, o[1][0]); o[1][1] = ffma2(vd1, a.y, o[1][1]);
            }
        }

        #pragma unroll
        for (int p = 0; p < 2; p++) {
            float2 e0 = unpack2(o[0][p]);
            float2 e1 = unpack2(o[1][p]);
            float r0[2] = {e0.x, e0.y};
            float r1[2] = {e1.x, e1.y};
            #pragma unroll
            for (int u = 0; u < 2; u++) {
                int il = i0 + p * 2 + u;
                int iglob = ig0 + il;
                float inv = s_inv[il];
                float out0 = r0[u] * inv - v0p[iglob];
                float out1 = r1[u] * inv - v1p[iglob];
                *(float2*)(g_act + ((size_t)b * TT + iglob) * DINP + h * KD + d0)
                    = make_float2(out0, out1);
            }
        }
    }
}

// ---------------------------------------------------------------------------
// Kernel 2 (fused MLP): h1 = relu(act@W1+b1); h2 = relu(h1@W2+b2);
// out = h2@Wo + bo. 16 rows/block, 128 threads, grid 256.
// Column-split warps: warp w owns cols [64w, 64w+64), lanes = 8 col x 4 row,
// thread tile 4 rows x 8 cols. W LDS.128 = 1 wavefront (8 distinct 16B);
// a staged per-chunk into registers (1-wf LDS.128, row-major s_a/s_h1).
// W panels (8 k-rows) cp.async double-buffered.
// ---------------------------------------------------------------------------
#define CKP 8
__global__ void __launch_bounds__(128) mlp_kernel(
    const float* __restrict__ W1, const float* __restrict__ b1,
    const float* __restrict__ W2, const float* __restrict__ b2,
    const float* __restrict__ Wo, const float* __restrict__ bo,
    float* __restrict__ out)
{
    __shared__ float s_a[16 * DINP];           // [row][k]  10KB
    __shared__ float s_h1[16 * HIDN];          // [row][k]  16KB
    __shared__ float s_w[2][CKP * HIDN];       // 2 x 8KB
    __shared__ float s_red[16][4];

    const int rbase = blockIdx.x * 16;
    const int t = threadIdx.x;
    const int wrp  = t >> 5;                   // 4 warps, each owns 64 cols
    const int lane = t & 31;
    const int c0 = wrp * 64 + (lane & 7) * 8;  // 8 col-threads x 8 cols
    const int r0 = (lane >> 3) * 4;            // 4 row-threads x 4 rows
    const uint32_t wsm = (uint32_t)__cvta_generic_to_shared(&s_w[0][0]);

    // prologue: W1 panel 0 -> buf 0 (async), act tile -> smem (sync loads)
    #pragma unroll
    for (int u = 0; u < 4; u++)
        cpa16(wsm + (uint32_t)(t + u * 128) * 16, W1 + (size_t)(t + u * 128) * 4);
    cpa_commit();
    {
        const float4* src = (const float4*)(g_act + (size_t)rbase * DINP);
        float4* dst = (float4*)s_a;
        #pragma unroll
        for (int n = t; n < 16 * DINP / 4; n += 128) dst[n] = src[n];
    }

    ull acc[4][4];
    {
        float4 bl = *(const float4*)(b1 + c0);
        float4 bh = *(const float4*)(b1 + c0 + 4);
        #pragma unroll
        for (int r = 0; r < 4; r++) {
            acc[r][0] = pack2(bl.x, bl.y); acc[r][1] = pack2(bl.z, bl.w);
            acc[r][2] = pack2(bh.x, bh.y); acc[r][3] = pack2(bh.z, bh.w);
        }
    }

    // ---- phase 1: k = 0..159 over W1
    const int NCH1 = DINP / CKP;   // 20
    for (int ch = 0; ch < NCH1; ch++) {
        if (ch + 1 < NCH1) {
            const uint32_t dstb = wsm + (uint32_t)(((ch + 1) & 1) * CKP * HIDN) * 4;
            const float* srcb = W1 + (size_t)(ch + 1) * CKP * HIDN;
            #pragma unroll
            for (int u = 0; u < 4; u++)
                cpa16(dstb + (uint32_t)(t + u * 128) * 16, srcb + (size_t)(t + u * 128) * 4);
            cpa_commit();
            cpa_wait<1>();
        } else {
            cpa_wait<0>();
        }
        __syncthreads();
        const float* wp = &s_w[ch & 1][0];
        const int kg0 = ch * CKP;
        // stage my 4 rows x 8 k of activations into registers (1-wf LDS.128s)
        float areg[4][CKP];
        #pragma unroll
        for (int r = 0; r < 4; r++) {
            float4 x = *(const float4*)&s_a[(r0 + r) * DINP + kg0];
            float4 y = *(const float4*)&s_a[(r0 + r) * DINP + kg0 + 4];
            areg[r][0] = x.x; areg[r][1] = x.y; areg[r][2] = x.z; areg[r][3] = x.w;
            areg[r][4] = y.x; areg[r][5] = y.y; areg[r][6] = y.z; areg[r][7] = y.w;
        }
        #pragma unroll
        for (int kk = 0; kk < CKP; kk++) {
            ulonglong2 w01 = *(const ulonglong2*)(wp + kk * HIDN + c0);
            ulonglong2 w23 = *(const ulonglong2*)(wp + kk * HIDN + c0 + 4);
            ull ad;
            ad = pack2(areg[0][kk], areg[0][kk]);
            acc[0][0] = ffma2(ad, w01.x, acc[0][0]); acc[0][1] = ffma2(ad, w01.y, acc[0][1]);
            acc[0][2] = ffma2(ad, w23.x, acc[0][2]); acc[0][3] = ffma2(ad, w23.y, acc[0][3]);
            ad = pack2(areg[1][kk], areg[1][kk]);
            acc[1][0] = ffma2(ad, w01.x, acc[1][0]); acc[1][1] = ffma2(ad, w01.y, acc[1][1]);
            acc[1][2] = ffma2(ad, w23.x, acc[1][2]); acc[1][3] = ffma2(ad, w23.y, acc[1][3]);
            ad = pack2(areg[2][kk], areg[2][kk]);
            acc[2][0] = ffma2(ad, w01.x, acc[2][0]); acc[2][1] = ffma2(ad, w01.y, acc[2][1]);
            acc[2][2] = ffma2(ad, w23.x, acc[2][2]); acc[2][3] = ffma2(ad, w23.y, acc[2][3]);
            ad = pack2(areg[3][kk], areg[3][kk]);
            acc[3][0] = ffma2(ad, w01.x, acc[3][0]); acc[3][1] = ffma2(ad, w01.y, acc[3][1]);
            acc[3][2] = ffma2(ad, w23.x, acc[3][2]); acc[3][3] = ffma2(ad, w23.y, acc[3][3]);
        }
        __syncthreads();
    }

    // ---- relu -> s_h1 (row-major), prefetch W2 panel 0
    #pragma unroll
    for (int u = 0; u < 4; u++)
        cpa16(wsm + (uint32_t)(t + u * 128) * 16, W2 + (size_t)(t + u * 128) * 4);
    cpa_commit();
    #pragma unroll
    for (int r = 0; r < 4; r++) {
        float2 p0 = unpack2(acc[r][0]), p1 = unpack2(acc[r][1]);
        float2 p2 = unpack2(acc[r][2]), p3 = unpack2(acc[r][3]);
        float* hrow = s_h1 + (r0 + r) * HIDN + c0;
        *(float4*)hrow = make_float4(fmaxf(p0.x, 0.f), fmaxf(p0.y, 0.f),
                                     fmaxf(p1.x, 0.f), fmaxf(p1.y, 0.f));
        *(float4*)(hrow + 4) = make_float4(fmaxf(p2.x, 0.f), fmaxf(p2.y, 0.f),
                                           fmaxf(p3.x, 0.f), fmaxf(p3.y, 0.f));
    }
    {
        float4 bl = *(const float4*)(b2 + c0);
        float4 bh = *(const float4*)(b2 + c0 + 4);
        #pragma unroll
        for (int r = 0; r < 4; r++) {
            acc[r][0] = pack2(bl.x, bl.y); acc[r][1] = pack2(bl.z, bl.w);
            acc[r][2] = pack2(bh.x, bh.y); acc[r][3] = pack2(bh.z, bh.w);
        }
    }
    __syncthreads();

    // ---- phase 2: k = 0..255 over W2, reading s_h1
    const int NCH2 = HIDN / CKP;   // 32
    for (int ch = 0; ch < NCH2; ch++) {
        if (ch + 1 < NCH2) {
            const uint32_t dstb = wsm + (uint32_t)(((ch + 1) & 1) * CKP * HIDN) * 4;
            const float* srcb = W2 + (size_t)(ch + 1) * CKP * HIDN;
            #pragma unroll
            for (int u = 0; u < 4; u++)
                cpa16(dstb + (uint32_t)(t + u * 128) * 16, srcb + (size_t)(t + u * 128) * 4);
            cpa_commit();
            cpa_wait<1>();
        } else {
            cpa_wait<0>();
        }
        __syncthreads();
        const float* wp = &s_w[ch & 1][0];
        const int kg0 = ch * CKP;
        float areg[4][CKP];
        #pragma unroll
        for (int r = 0; r < 4; r++) {
            float4 x = *(const float4*)&s_h1[(r0 + r) * HIDN + kg0];
            float4 y = *(const float4*)&s_h1[(r0 + r) * HIDN + kg0 + 4];
            areg[r][0] = x.x; areg[r][1] = x.y; areg[r][2] = x.z; areg[r][3] = x.w;
            areg[r][4] = y.x; areg[r][5] = y.y; areg[r][6] = y.z; areg[r][7] = y.w;
        }
        #pragma unroll
        for (int kk = 0; kk < CKP; kk++) {
            ulonglong2 w01 = *(const ulonglong2*)(wp + kk * HIDN + c0);
            ulonglong2 w23 = *(const ulonglong2*)(wp + kk * HIDN + c0 + 4);
            ull ad;
            ad = pack2(areg[0][kk], areg[0][kk]);
            acc[0][0] = ffma2(ad, w01.x, acc[0][0]); acc[0][1] = ffma2(ad, w01.y, acc[0][1]);
            acc[0][2] = ffma2(ad, w23.x, acc[0][2]); acc[0][3] = ffma2(ad, w23.y, acc[0][3]);
            ad = pack2(areg[1][kk], areg[1][kk]);
            acc[1][0] = ffma2(ad, w01.x, acc[1][0]); acc[1][1] = ffma2(ad, w01.y, acc[1][1]);
            acc[1][2] = ffma2(ad, w23.x, acc[1][2]); acc[1][3] = ffma2(ad, w23.y, acc[1][3]);
            ad = pack2(areg[2][kk], areg[2][kk]);
            acc[2][0] = ffma2(ad, w01.x, acc[2][0]); acc[2][1] = ffma2(ad, w01.y, acc[2][1]);
            acc[2][2] = ffma2(ad, w23.x, acc[2][2]); acc[2][3] = ffma2(ad, w23.y, acc[2][3]);
            ad = pack2(areg[3][kk], areg[3][kk]);
            acc[3][0] = ffma2(ad, w01.x, acc[3][0]); acc[3][1] = ffma2(ad, w01.y, acc[3][1]);
            acc[3][2] = ffma2(ad, w23.x, acc[3][2]); acc[3][3] = ffma2(ad, w23.y, acc[3][3]);
        }
        __syncthreads();
    }

    // ---- relu + dot with my 8-col Wo slice; reduce over 8 col-threads
    float4 wl = *(const float4*)(Wo + c0);
    float4 wh = *(const float4*)(Wo + c0 + 4);
    float p[4];
    #pragma unroll
    for (int r = 0; r < 4; r++) {
        float2 p0 = unpack2(acc[r][0]), p1 = unpack2(acc[r][1]);
        float2 p2 = unpack2(acc[r][2]), p3 = unpack2(acc[r][3]);
        float s = 0.f;
        s = fmaf(fmaxf(p0.x, 0.f), wl.x, s);
        s = fmaf(fmaxf(p0.y, 0.f), wl.y, s);
        s = fmaf(fmaxf(p1.x, 0.f), wl.z, s);
        s = fmaf(fmaxf(p1.y, 0.f), wl.w, s);
        s = fmaf(fmaxf(p2.x, 0.f), wh.x, s);
        s = fmaf(fmaxf(p2.y, 0.f), wh.y, s);
        s = fmaf(fmaxf(p3.x, 0.f), wh.z, s);
        s = fmaf(fmaxf(p3.y, 0.f), wh.w, s);
        p[r] = s;
    }
    #pragma unroll
    for (int off = 4; off; off >>= 1) {
        #pragma unroll
        for (int r = 0; r < 4; r++)
            p[r] += __shfl_down_sync(0xffffffffu, p[r], off, 8);
    }
    if ((lane & 7) == 0) {
        #pragma unroll
        for (int r = 0; r < 4; r++)
            s_red[r0 + r][wrp] = p[r];
    }
    __syncthreads();
    if (t < 16)
        out[rbase + t] = s_red[t][0] + s_red[t][1] + s_red[t][2] + s_red[t][3] + bo[0];
}

// ---------------------------------------------------------------------------
extern "C" void kernel_launch(void* const* d_in, const int* in_sizes, int n_in,
                              void* d_out, int out_size)
{
    (void)in_sizes; (void)n_in; (void)out_size;
    const float* state = (const float*)d_in[0];
    const float* Wq    = (const float*)d_in[1];
    const float* Wk    = (const float*)d_in[2];
    const float* Wv    = (const float*)d_in[3];
    const float* W1    = (const float*)d_in[4];
    const float* b1    = (const float*)d_in[5];
    const float* W2    = (const float*)d_in[6];
    const float* b2    = (const float*)d_in[7];
    const float* Wo    = (const float*)d_in[8];
    const float* bo    = (const float*)d_in[9];
    float* out = (float*)d_out;

    proj_kernel<<<384, 256>>>(state, Wq, Wk, Wv);
    attn_kernel<<<BB * HH * 2, 256>>>();
    mlp_kernel<<<(BB * TT) / 16, 128>>>(W1, b1, W2, b2, Wo, bo, out);
}

// round 8
// speedup vs baseline: 1.4141x; 1.0932x over previous
#include <cuda_runtime.h>
#include <cstdint>

#define BB   32
#define TT   128
#define KD   32
#define HH   4
#define DINP 160
#define HIDN 256

// Scratch (static device global; no allocation).
__device__ float g_act[BB * TT * DINP];     // [x | state]  4096 x 160

typedef unsigned long long ull;

__device__ __forceinline__ ull ffma2(ull a, ull b, ull c) {
    ull d;
    asm("fma.rn.f32x2 %0, %1, %2, %3;" : "=l"(d) : "l"(a), "l"(b), "l"(c));
    return d;
}
__device__ __forceinline__ ull pack2(float x, float y) {
    ull r;
    asm("mov.b64 %0, {%1, %2};" : "=l"(r) : "f"(x), "f"(y));
    return r;
}
__device__ __forceinline__ float2 unpack2(ull v) {
    float x, y;
    asm("mov.b64 {%0, %1}, %2;" : "=f"(x), "=f"(y) : "l"(v));
    return make_float2(x, y);
}
__device__ __forceinline__ void cpa16(uint32_t dst_smem, const void* src) {
    asm volatile("cp.async.cg.shared.global [%0], [%1], 16;\n"
                 :: "r"(dst_smem), "l"(src) : "memory");
}
__device__ __forceinline__ void cpa_commit() {
    asm volatile("cp.async.commit_group;\n" ::: "memory");
}
template <int N>
__device__ __forceinline__ void cpa_wait() {
    asm volatile("cp.async.wait_group %0;\n" :: "n"(N) : "memory");
}

// ---------------------------------------------------------------------------
// Fused attention smem layout (floats). P aliases the proj staging region.
// ---------------------------------------------------------------------------
#define OFF_ST    0            // stateT [32][pitch 132]       4224
#define OFF_WQ    4224         // WqT-slice [32][pitch 68]     2176
#define OFF_WKV   6400         // Wk|Wv slice [32][pitch 68]   2176  (end 8576)
#define OFF_P     0            // P [128][64]                  8192  (alias)
#define OFF_KT    8576         // kT [32][128]                 4096
#define OFF_VT    12672        // vT [32][128]                 4096
#define OFF_QT    16768        // qT [32][64]                  2048
#define OFF_MX    18816        // [4][64]
#define OFF_SM    19072        // [4][64]
#define OFF_INV   19328        // [64]
#define ATTN_SMEM_FLOATS 19392
#define ATTN_SMEM_BYTES  (ATTN_SMEM_FLOATS * 4)

// ---------------------------------------------------------------------------
// Kernel 1 (fused QKV-proj + masked attention), 64 query rows of one (b,h).
// grid 256 = (b, h, ihalf), 256 threads, 2 CTA/SM.
// ---------------------------------------------------------------------------
__global__ void __launch_bounds__(256, 2) attn_kernel(
    const float* __restrict__ state,
    const float* __restrict__ Wq,
    const float* __restrict__ Wk,
    const float* __restrict__ Wv)
{
    extern __shared__ float sm[];
    const int bx = blockIdx.x;
    const int b = bx >> 3, h = (bx >> 1) & 3, ihalf = bx & 1;
    const int t = threadIdx.x;
    const int ig0 = ihalf * 64;

    float* sT    = sm + OFF_ST;
    float* swq   = sm + OFF_WQ;
    float* swkv  = sm + OFF_WKV;
    float* P     = sm + OFF_P;
    float* kT    = sm + OFF_KT;
    float* vT    = sm + OFF_VT;
    float* qT    = sm + OFF_QT;
    float* s_mx  = sm + OFF_MX;
    float* s_sm  = sm + OFF_SM;
    float* s_inv = sm + OFF_INV;

    // ---- stage stateT [c][j] (pitch 132) and weight slices (pitch 68)
    {
        int r = t >> 1, c0 = (t & 1) * 16;
        const float4* p = (const float4*)(state + ((size_t)b * TT + r) * KD + c0);
        #pragma unroll
        for (int w = 0; w < 4; w++) {
            float4 v = p[w];
            sT[(c0 + 4 * w + 0) * 132 + r] = v.x;
            sT[(c0 + 4 * w + 1) * 132 + r] = v.y;
            sT[(c0 + 4 * w + 2) * 132 + r] = v.z;
            sT[(c0 + 4 * w + 3) * 132 + r] = v.w;
        }
    }
    {
        int r = t >> 3, q = t & 7;      // 32 rows x 8 float4-chunks of the 32-col slice
        size_t src = (size_t)r * (KD * HH) + h * KD + q * 4;
        *(float4*)&swq[r * 68 + q * 4]        = *(const float4*)(Wq + src);
        *(float4*)&swkv[r * 68 + q * 4]       = *(const float4*)(Wk + src);
        *(float4*)&swkv[r * 68 + 32 + q * 4]  = *(const float4*)(Wv + src);
    }
    __syncthreads();

    // ---- KV projection: 128 rows x 64 cols (K|V), tile 8r x 4c per thread
    {
        const int rg = t & 15, cg = t >> 4;
        const int j0 = rg * 8, c0 = cg * 4;
        ull acc[8][2];
        #pragma unroll
        for (int r = 0; r < 8; r++) { acc[r][0] = 0ull; acc[r][1] = 0ull; }

        #pragma unroll 8
        for (int k = 0; k < KD; k++) {
            float4 a0 = *(const float4*)&sT[k * 132 + j0];
            float4 a1 = *(const float4*)&sT[k * 132 + j0 + 4];
            ulonglong2 b2 = *(const ulonglong2*)&swkv[k * 68 + c0];
            ull ad;
            ad = pack2(a0.x, a0.x); acc[0][0] = ffma2(ad, b2.x, acc[0][0]); acc[0][1] = ffma2(ad, b2.y, acc[0][1]);
            ad = pack2(a0.y, a0.y); acc[1][0] = ffma2(ad, b2.x, acc[1][0]); acc[1][1] = ffma2(ad, b2.y, acc[1][1]);
            ad = pack2(a0.z, a0.z); acc[2][0] = ffma2(ad, b2.x, acc[2][0]); acc[2][1] = ffma2(ad, b2.y, acc[2][1]);
            ad = pack2(a0.w, a0.w); acc[3][0] = ffma2(ad, b2.x, acc[3][0]); acc[3][1] = ffma2(ad, b2.y, acc[3][1]);
            ad = pack2(a1.x, a1.x); acc[4][0] = ffma2(ad, b2.x, acc[4][0]); acc[4][1] = ffma2(ad, b2.y, acc[4][1]);
            ad = pack2(a1.y, a1.y); acc[5][0] = ffma2(ad, b2.x, acc[5][0]); acc[5][1] = ffma2(ad, b2.y, acc[5][1]);
            ad = pack2(a1.z, a1.z); acc[6][0] = ffma2(ad, b2.x, acc[6][0]); acc[6][1] = ffma2(ad, b2.y, acc[6][1]);
            ad = pack2(a1.w, a1.w); acc[7][0] = ffma2(ad, b2.x, acc[7][0]); acc[7][1] = ffma2(ad, b2.y, acc[7][1]);
        }

        float cs[4][8];
        #pragma unroll
        for (int r = 0; r < 8; r++) {
            float2 e0 = unpack2(acc[r][0]), e1 = unpack2(acc[r][1]);
            cs[0][r] = e0.x; cs[1][r] = e0.y; cs[2][r] = e1.x; cs[3][r] = e1.y;
        }
        #pragma unroll
        for (int cc = 0; cc < 4; cc++) {
            int c = c0 + cc;
            float* dst = (c < KD) ? (kT + c * TT + j0) : (vT + (c - KD) * TT + j0);
            *(float4*)dst       = make_float4(cs[cc][0], cs[cc][1], cs[cc][2], cs[cc][3]);
            *(float4*)(dst + 4) = make_float4(cs[cc][4], cs[cc][5], cs[cc][6], cs[cc][7]);
        }
    }

    // ---- Q projection (threads 0-127); concat-tail copy (threads 128-255, h==0)
    if (t < 128) {
        const int rg = t & 15, cg = t >> 4;
        const int i0 = rg * 4, c0 = cg * 4;
        ull acc[4][2];
        #pragma unroll
        for (int r = 0; r < 4; r++) { acc[r][0] = 0ull; acc[r][1] = 0ull; }

        #pragma unroll 8
        for (int k = 0; k < KD; k++) {
            float4 a0 = *(const float4*)&sT[k * 132 + ig0 + i0];
            ulonglong2 b2 = *(const ulonglong2*)&swq[k * 68 + c0];
            ull ad;
            ad = pack2(a0.x, a0.x); acc[0][0] = ffma2(ad, b2.x, acc[0][0]); acc[0][1] = ffma2(ad, b2.y, acc[0][1]);
            ad = pack2(a0.y, a0.y); acc[1][0] = ffma2(ad, b2.x, acc[1][0]); acc[1][1] = ffma2(ad, b2.y, acc[1][1]);
            ad = pack2(a0.z, a0.z); acc[2][0] = ffma2(ad, b2.x, acc[2][0]); acc[2][1] = ffma2(ad, b2.y, acc[2][1]);
            ad = pack2(a0.w, a0.w); acc[3][0] = ffma2(ad, b2.x, acc[3][0]); acc[3][1] = ffma2(ad, b2.y, acc[3][1]);
        }
        float qs[4][4];
        #pragma unroll
        for (int r = 0; r < 4; r++) {
            float2 e0 = unpack2(acc[r][0]), e1 = unpack2(acc[r][1]);
            qs[0][r] = e0.x; qs[1][r] = e0.y; qs[2][r] = e1.x; qs[3][r] = e1.y;
        }
        #pragma unroll
        for (int cc = 0; cc < 4; cc++)
            *(float4*)&qT[(c0 + cc) * 64 + i0] =
                make_float4(qs[cc][0], qs[cc][1], qs[cc][2], qs[cc][3]);
    } else if (h == 0) {
        int n = t - 128;                           // 512 float4s, 4 per thread
        #pragma unroll
        for (int u = 0; u < 4; u++) {
            int m = n + u * 128;
            int row = m >> 3, c = (m & 7) * 4;
            size_t gr = (size_t)b * TT + ig0 + row;
            float4 v = *(const float4*)(state + gr * KD + c);
            *(float4*)(g_act + gr * DINP + 4 * KD + c) = v;
        }
    }
    __syncthreads();

    // ---- GEMM1: S^T[j][i] = K[j]·Q[i]; tile 8i x 4j (reads smem kT/qT)
    {
        const int ig = t >> 5, jg = t & 31;
        const int i0 = ig * 8, j0 = jg * 4;
        ull acc[4][4];
        #pragma unroll
        for (int c = 0; c < 4; c++)
            #pragma unroll
            for (int p = 0; p < 4; p++) acc[c][p] = 0ull;

        #pragma unroll 4
        for (int kk = 0; kk < KD; kk++) {
            const float* qrow = qT + kk * 64 + i0;
            ulonglong2 a01 = *(const ulonglong2*)qrow;
            ulonglong2 a23 = *(const ulonglong2*)(qrow + 4);
            float4 bj = *(const float4*)(kT + kk * TT + j0);
            ull bd;
            bd = pack2(bj.x, bj.x);
            acc[0][0] = ffma2(bd, a01.x, acc[0][0]); acc[0][1] = ffma2(bd, a01.y, acc[0][1]);
            acc[0][2] = ffma2(bd, a23.x, acc[0][2]); acc[0][3] = ffma2(bd, a23.y, acc[0][3]);
            bd = pack2(bj.y, bj.y);
            acc[1][0] = ffma2(bd, a01.x, acc[1][0]); acc[1][1] = ffma2(bd, a01.y, acc[1][1]);
            acc[1][2] = ffma2(bd, a23.x, acc[1][2]); acc[1][3] = ffma2(bd, a23.y, acc[1][3]);
            bd = pack2(bj.z, bj.z);
            acc[2][0] = ffma2(bd, a01.x, acc[2][0]); acc[2][1] = ffma2(bd, a01.y, acc[2][1]);
            acc[2][2] = ffma2(bd, a23.x, acc[2][2]); acc[2][3] = ffma2(bd, a23.y, acc[2][3]);
            bd = pack2(bj.w, bj.w);
            acc[3][0] = ffma2(bd, a01.x, acc[3][0]); acc[3][1] = ffma2(bd, a01.y, acc[3][1]);
            acc[3][2] = ffma2(bd, a23.x, acc[3][2]); acc[3][3] = ffma2(bd, a23.y, acc[3][3]);
        }

        __syncthreads();    // proj staging fully consumed before P overwrites it
        #pragma unroll
        for (int c = 0; c < 4; c++) {
            int jglob = j0 + c;
            int rd = jglob - ig0 - i0;          // diag position within my 8 i's
            if (rd >= 0 && rd < 8) {
                int p = rd >> 1, hi = rd & 1;
                float2 v = unpack2(acc[c][p]);
                if (hi) v.y = -1e30f; else v.x = -1e30f;
                acc[c][p] = pack2(v.x, v.y);
            }
            ull* dst = (ull*)&P[jglob * 64 + i0];
            dst[0] = acc[c][0]; dst[1] = acc[c][1];
            dst[2] = acc[c][2]; dst[3] = acc[c][3];
        }
    }
    __syncthreads();

    // ---- softmax (over j) on P, in place
    {
        const float scale = 0.17677669529663687f;   // 1/sqrt(32)
        const int i = t & 63, q = t >> 6;
        float mx = -1e30f;
        #pragma unroll 8
        for (int jj = 0; jj < 32; jj++)
            mx = fmaxf(mx, P[(q * 32 + jj) * 64 + i]);
        s_mx[q * 64 + i] = mx;
        __syncthreads();
        float m = fmaxf(fmaxf(s_mx[0 * 64 + i], s_mx[1 * 64 + i]),
                        fmaxf(s_mx[2 * 64 + i], s_mx[3 * 64 + i]));
        float sum = 0.f;
        #pragma unroll 8
        for (int jj = 0; jj < 32; jj++) {
            int idx = (q * 32 + jj) * 64 + i;
            float e = __expf((P[idx] - m) * scale);
            P[idx] = e;
            sum += e;
        }
        s_sm[q * 64 + i] = sum;
    }
    __syncthreads();
    if (t < 64)
        s_inv[t] = 1.f / (s_sm[0 * 64 + t] + s_sm[1 * 64 + t] +
                          s_sm[2 * 64 + t] + s_sm[3 * 64 + t]);
    __syncthreads();

    // ---- GEMM2: O[i][d] = sum_j P[j][i] * V[j][d]; tile 4i x 2d (smem vT)
    {
        const int ig = t & 15, dg = t >> 4;
        const int i0 = ig * 4, d0 = dg * 2;
        ull o[2][2];
        o[0][0] = 0ull; o[0][1] = 0ull; o[1][0] = 0ull; o[1][1] = 0ull;
        const float* v0p = vT + d0 * TT;
        const float* v1p = v0p + TT;

        for (int j = 0; j < TT; j += 4) {
            float4 v40 = *(const float4*)(v0p + j);
            float4 v41 = *(const float4*)(v1p + j);
            float va0[4] = {v40.x, v40.y, v40.z, v40.w};
            float va1[4] = {v41.x, v41.y, v41.z, v41.w};
            #pragma unroll
            for (int u = 0; u < 4; u++) {
                ulonglong2 a = *(const ulonglong2*)&P[(j + u) * 64 + i0];
                ull vd0 = pack2(va0[u], va0[u]);
                ull vd1 = pack2(va1[u], va1[u]);
                o[0][0] = ffma2(vd0, a.x, o[0][0]); o[0][1] = ffma2(vd0, a.y, o[0][1]);
                o[1][0] = ffma2(vd1, a.x, o[1][0]); o[1][1] = ffma2(vd1, a.y, o[1][1]);
            }
        }

        #pragma unroll
        for (int p = 0; p < 2; p++) {
            float2 e0 = unpack2(o[0][p]);
            float2 e1 = unpack2(o[1][p]);
            float r0[2] = {e0.x, e0.y};
            float r1[2] = {e1.x, e1.y};
            #pragma unroll
            for (int u = 0; u < 2; u++) {
                int il = i0 + p * 2 + u;
                int iglob = ig0 + il;
                float inv = s_inv[il];
                float out0 = r0[u] * inv - v0p[iglob];
                float out1 = r1[u] * inv - v1p[iglob];
                *(float2*)(g_act + ((size_t)b * TT + iglob) * DINP + h * KD + d0)
                    = make_float2(out0, out1);
            }
        }
    }
}

// ---------------------------------------------------------------------------
// Kernel 2 (fused MLP) — byte-identical to the R5 (67.6us) version.
// 16 rows/block, 128 threads, grid 256.
// ---------------------------------------------------------------------------
#define CKP 8
__global__ void __launch_bounds__(128) mlp_kernel(
    const float* __restrict__ W1, const float* __restrict__ b1,
    const float* __restrict__ W2, const float* __restrict__ b2,
    const float* __restrict__ Wo, const float* __restrict__ bo,
    float* __restrict__ out)
{
    __shared__ float s_a[16 * DINP];           // [row][k]  10KB
    __shared__ float s_h1[16 * HIDN];          // [row][k]  16KB
    __shared__ float s_w[2][CKP * HIDN];       // 2 x 8KB

    const int rbase = blockIdx.x * 16;
    const int t = threadIdx.x;
    const int c0 = (t & 31) * 8;
    const int r0 = (t >> 5) * 4;
    const uint32_t wsm = (uint32_t)__cvta_generic_to_shared(&s_w[0][0]);

    #pragma unroll
    for (int u = 0; u < 4; u++)
        cpa16(wsm + (uint32_t)(t + u * 128) * 16, W1 + (size_t)(t + u * 128) * 4);
    cpa_commit();
    {
        const float4* src = (const float4*)(g_act + (size_t)rbase * DINP);
        float4* dst = (float4*)s_a;
        #pragma unroll
        for (int n = t; n < 16 * DINP / 4; n += 128) dst[n] = src[n];
    }

    ull acc[4][4];
    {
        float4 bl = *(const float4*)(b1 + c0);
        float4 bh = *(const float4*)(b1 + c0 + 4);
        #pragma unroll
        for (int r = 0; r < 4; r++) {
            acc[r][0] = pack2(bl.x, bl.y); acc[r][1] = pack2(bl.z, bl.w);
            acc[r][2] = pack2(bh.x, bh.y); acc[r][3] = pack2(bh.z, bh.w);
        }
    }

    const int NCH1 = DINP / CKP;   // 20
    for (int ch = 0; ch < NCH1; ch++) {
        if (ch + 1 < NCH1) {
            const uint32_t dstb = wsm + (uint32_t)(((ch + 1) & 1) * CKP * HIDN) * 4;
            const float* srcb = W1 + (size_t)(ch + 1) * CKP * HIDN;
            #pragma unroll
            for (int u = 0; u < 4; u++)
                cpa16(dstb + (uint32_t)(t + u * 128) * 16, srcb + (size_t)(t + u * 128) * 4);
            cpa_commit();
            cpa_wait<1>();
        } else {
            cpa_wait<0>();
        }
        __syncthreads();
        const float* wp = &s_w[ch & 1][0];
        const int kg0 = ch * CKP;
        #pragma unroll
        for (int kk = 0; kk < CKP; kk++) {
            ulonglong2 w01 = *(const ulonglong2*)(wp + kk * HIDN + c0);
            ulonglong2 w23 = *(const ulonglong2*)(wp + kk * HIDN + c0 + 4);
            ull ad;
            ad = pack2(s_a[(r0 + 0) * DINP + kg0 + kk], s_a[(r0 + 0) * DINP + kg0 + kk]);
            acc[0][0] = ffma2(ad, w01.x, acc[0][0]); acc[0][1] = ffma2(ad, w01.y, acc[0][1]);
            acc[0][2] = ffma2(ad, w23.x, acc[0][2]); acc[0][3] = ffma2(ad, w23.y, acc[0][3]);
            ad = pack2(s_a[(r0 + 1) * DINP + kg0 + kk], s_a[(r0 + 1) * DINP + kg0 + kk]);
            acc[1][0] = ffma2(ad, w01.x, acc[1][0]); acc[1][1] = ffma2(ad, w01.y, acc[1][1]);
            acc[1][2] = ffma2(ad, w23.x, acc[1][2]); acc[1][3] = ffma2(ad, w23.y, acc[1][3]);
            ad = pack2(s_a[(r0 + 2) * DINP + kg0 + kk], s_a[(r0 + 2) * DINP + kg0 + kk]);
            acc[2][0] = ffma2(ad, w01.x, acc[2][0]); acc[2][1] = ffma2(ad, w01.y, acc[2][1]);
            acc[2][2] = ffma2(ad, w23.x, acc[2][2]); acc[2][3] = ffma2(ad, w23.y, acc[2][3]);
            ad = pack2(s_a[(r0 + 3) * DINP + kg0 + kk], s_a[(r0 + 3) * DINP + kg0 + kk]);
            acc[3][0] = ffma2(ad, w01.x, acc[3][0]); acc[3][1] = ffma2(ad, w01.y, acc[3][1]);
            acc[3][2] = ffma2(ad, w23.x, acc[3][2]); acc[3][3] = ffma2(ad, w23.y, acc[3][3]);
        }
        __syncthreads();
    }

    #pragma unroll
    for (int u = 0; u < 4; u++)
        cpa16(wsm + (uint32_t)(t + u * 128) * 16, W2 + (size_t)(t + u * 128) * 4);
    cpa_commit();
    #pragma unroll
    for (int r = 0; r < 4; r++) {
        float2 p0 = unpack2(acc[r][0]), p1 = unpack2(acc[r][1]);
        float2 p2 = unpack2(acc[r][2]), p3 = unpack2(acc[r][3]);
        float* hrow = s_h1 + (r0 + r) * HIDN + c0;
        *(float4*)hrow = make_float4(fmaxf(p0.x, 0.f), fmaxf(p0.y, 0.f),
                                     fmaxf(p1.x, 0.f), fmaxf(p1.y, 0.f));
        *(float4*)(hrow + 4) = make_float4(fmaxf(p2.x, 0.f), fmaxf(p2.y, 0.f),
                                           fmaxf(p3.x, 0.f), fmaxf(p3.y, 0.f));
    }
    {
        float4 bl = *(const float4*)(b2 + c0);
        float4 bh = *(const float4*)(b2 + c0 + 4);
        #pragma unroll
        for (int r = 0; r < 4; r++) {
            acc[r][0] = pack2(bl.x, bl.y); acc[r][1] = pack2(bl.z, bl.w);
            acc[r][2] = pack2(bh.x, bh.y); acc[r][3] = pack2(bh.z, bh.w);
        }
    }
    __syncthreads();

    const int NCH2 = HIDN / CKP;   // 32
    for (int ch = 0; ch < NCH2; ch++) {
        if (ch + 1 < NCH2) {
            const uint32_t dstb = wsm + (uint32_t)(((ch + 1) & 1) * CKP * HIDN) * 4;
            const float* srcb = W2 + (size_t)(ch + 1) * CKP * HIDN;
            #pragma unroll
            for (int u = 0; u < 4; u++)
                cpa16(dstb + (uint32_t)(t + u * 128) * 16, srcb + (size_t)(t + u * 128) * 4);
            cpa_commit();
            cpa_wait<1>();
        } else {
            cpa_wait<0>();
        }
        __syncthreads();
        const float* wp = &s_w[ch & 1][0];
        const int kg0 = ch * CKP;
        #pragma unroll
        for (int kk = 0; kk < CKP; kk++) {
            ulonglong2 w01 = *(const ulonglong2*)(wp + kk * HIDN + c0);
            ulonglong2 w23 = *(const ulonglong2*)(wp + kk * HIDN + c0 + 4);
            ull ad;
            ad = pack2(s_h1[(r0 + 0) * HIDN + kg0 + kk], s_h1[(r0 + 0) * HIDN + kg0 + kk]);
            acc[0][0] = ffma2(ad, w01.x, acc[0][0]); acc[0][1] = ffma2(ad, w01.y, acc[0][1]);
            acc[0][2] = ffma2(ad, w23.x, acc[0][2]); acc[0][3] = ffma2(ad, w23.y, acc[0][3]);
            ad = pack2(s_h1[(r0 + 1) * HIDN + kg0 + kk], s_h1[(r0 + 1) * HIDN + kg0 + kk]);
            acc[1][0] = ffma2(ad, w01.x, acc[1][0]); acc[1][1] = ffma2(ad, w01.y, acc[1][1]);
            acc[1][2] = ffma2(ad, w23.x, acc[1][2]); acc[1][3] = ffma2(ad, w23.y, acc[1][3]);
            ad = pack2(s_h1[(r0 + 2) * HIDN + kg0 + kk], s_h1[(r0 + 2) * HIDN + kg0 + kk]);
            acc[2][0] = ffma2(ad, w01.x, acc[2][0]); acc[2][1] = ffma2(ad, w01.y, acc[2][1]);
            acc[2][2] = ffma2(ad, w23.x, acc[2][2]); acc[2][3] = ffma2(ad, w23.y, acc[2][3]);
            ad = pack2(s_h1[(r0 + 3) * HIDN + kg0 + kk], s_h1[(r0 + 3) * HIDN + kg0 + kk]);
            acc[3][0] = ffma2(ad, w01.x, acc[3][0]); acc[3][1] = ffma2(ad, w01.y, acc[3][1]);
            acc[3][2] = ffma2(ad, w23.x, acc[3][2]); acc[3][3] = ffma2(ad, w23.y, acc[3][3]);
        }
        __syncthreads();
    }

    float4 wl = *(const float4*)(Wo + c0);
    float4 wh = *(const float4*)(Wo + c0 + 4);
    float p[4];
    #pragma unroll
    for (int r = 0; r < 4; r++) {
        float2 p0 = unpack2(acc[r][0]), p1 = unpack2(acc[r][1]);
        float2 p2 = unpack2(acc[r][2]), p3 = unpack2(acc[r][3]);
        float s = 0.f;
        s = fmaf(fmaxf(p0.x, 0.f), wl.x, s);
        s = fmaf(fmaxf(p0.y, 0.f), wl.y, s);
        s = fmaf(fmaxf(p1.x, 0.f), wl.z, s);
        s = fmaf(fmaxf(p1.y, 0.f), wl.w, s);
        s = fmaf(fmaxf(p2.x, 0.f), wh.x, s);
        s = fmaf(fmaxf(p2.y, 0.f), wh.y, s);
        s = fmaf(fmaxf(p3.x, 0.f), wh.z, s);
        s = fmaf(fmaxf(p3.y, 0.f), wh.w, s);
        p[r] = s;
    }
    #pragma unroll
    for (int off = 16; off; off >>= 1) {
        #pragma unroll
        for (int r = 0; r < 4; r++)
            p[r] += __shfl_down_sync(0xffffffffu, p[r], off);
    }
    if ((t & 31) == 0) {
        float bv = bo[0];
        #pragma unroll
        for (int r = 0; r < 4; r++)
            out[rbase + r0 + r] = p[r] + bv;
    }
}

// ---------------------------------------------------------------------------
extern "C" void kernel_launch(void* const* d_in, const int* in_sizes, int n_in,
                              void* d_out, int out_size)
{
    (void)in_sizes; (void)n_in; (void)out_size;
    const float* state = (const float*)d_in[0];
    const float* Wq    = (const float*)d_in[1];
    const float* Wk    = (const float*)d_in[2];
    const float* Wv    = (const float*)d_in[3];
    const float* W1    = (const float*)d_in[4];
    const float* b1    = (const float*)d_in[5];
    const float* W2    = (const float*)d_in[6];
    const float* b2    = (const float*)d_in[7];
    const float* Wo    = (const float*)d_in[8];
    const float* bo    = (const float*)d_in[9];
    float* out = (float*)d_out;

    cudaFuncSetAttribute(attn_kernel,
                         cudaFuncAttributeMaxDynamicSharedMemorySize,
                         ATTN_SMEM_BYTES);
    attn_kernel<<<BB * HH * 2, 256, ATTN_SMEM_BYTES>>>(state, Wq, Wk, Wv);
    mlp_kernel<<<(BB * TT) / 16, 128>>>(W1, b1, W2, b2, Wo, bo, out);
}

// round 9
// speedup vs baseline: 1.6728x; 1.1829x over previous
#include <cuda_runtime.h>
#include <cstdint>

#define BB   32
#define TT   128
#define KD   32
#define HH   4
#define DINP 160
#define HIDN 256

// Scratch (static device global; no allocation).
__device__ float g_act[BB * TT * DINP];     // [x | state]  4096 x 160

typedef unsigned long long ull;

__device__ __forceinline__ ull ffma2(ull a, ull b, ull c) {
    ull d;
    asm("fma.rn.f32x2 %0, %1, %2, %3;" : "=l"(d) : "l"(a), "l"(b), "l"(c));
    return d;
}
__device__ __forceinline__ ull pack2(float x, float y) {
    ull r;
    asm("mov.b64 %0, {%1, %2};" : "=l"(r) : "f"(x), "f"(y));
    return r;
}
__device__ __forceinline__ float2 unpack2(ull v) {
    float x, y;
    asm("mov.b64 {%0, %1}, %2;" : "=f"(x), "=f"(y) : "l"(v));
    return make_float2(x, y);
}
__device__ __forceinline__ void cpa16(uint32_t dst_smem, const void* src) {
    asm volatile("cp.async.cg.shared.global [%0], [%1], 16;\n"
                 :: "r"(dst_smem), "l"(src) : "memory");
}
__device__ __forceinline__ void cpa_commit() {
    asm volatile("cp.async.commit_group;\n" ::: "memory");
}
template <int N>
__device__ __forceinline__ void cpa_wait() {
    asm volatile("cp.async.wait_group %0;\n" :: "n"(N) : "memory");
}

// ---------------------------------------------------------------------------
// Fused attention smem layout (floats). P aliases the proj staging region.
// ---------------------------------------------------------------------------
#define OFF_ST    0            // stateT [32][pitch 132]       4224
#define OFF_WQ    4224         // WqT-slice [32][pitch 68]     2176
#define OFF_WKV   6400         // Wk|Wv slice [32][pitch 68]   2176  (end 8576)
#define OFF_P     0            // P [128][64]                  8192  (alias)
#define OFF_KT    8576         // kT [32][128]                 4096
#define OFF_VT    12672        // vT [32][128]                 4096
#define OFF_QT    16768        // qT [32][64]                  2048
#define OFF_MX    18816        // [4][64]
#define OFF_SM    19072        // [4][64]
#define OFF_INV   19328        // [64]
#define ATTN_SMEM_FLOATS 19392
#define ATTN_SMEM_BYTES  (ATTN_SMEM_FLOATS * 4)

// ---------------------------------------------------------------------------
// Kernel 1 (fused QKV-proj + masked attention), 64 query rows of one (b,h).
// grid 256 = (b, h, ihalf), 256 threads, 2 CTA/SM.  (identical to R8)
// ---------------------------------------------------------------------------
__global__ void __launch_bounds__(256, 2) attn_kernel(
    const float* __restrict__ state,
    const float* __restrict__ Wq,
    const float* __restrict__ Wk,
    const float* __restrict__ Wv)
{
    extern __shared__ float sm[];
    const int bx = blockIdx.x;
    const int b = bx >> 3, h = (bx >> 1) & 3, ihalf = bx & 1;
    const int t = threadIdx.x;
    const int ig0 = ihalf * 64;

    float* sT    = sm + OFF_ST;
    float* swq   = sm + OFF_WQ;
    float* swkv  = sm + OFF_WKV;
    float* P     = sm + OFF_P;
    float* kT    = sm + OFF_KT;
    float* vT    = sm + OFF_VT;
    float* qT    = sm + OFF_QT;
    float* s_mx  = sm + OFF_MX;
    float* s_sm  = sm + OFF_SM;
    float* s_inv = sm + OFF_INV;

    // ---- stage stateT [c][j] (pitch 132) and weight slices (pitch 68)
    {
        int r = t >> 1, c0 = (t & 1) * 16;
        const float4* p = (const float4*)(state + ((size_t)b * TT + r) * KD + c0);
        #pragma unroll
        for (int w = 0; w < 4; w++) {
            float4 v = p[w];
            sT[(c0 + 4 * w + 0) * 132 + r] = v.x;
            sT[(c0 + 4 * w + 1) * 132 + r] = v.y;
            sT[(c0 + 4 * w + 2) * 132 + r] = v.z;
            sT[(c0 + 4 * w + 3) * 132 + r] = v.w;
        }
    }
    {
        int r = t >> 3, q = t & 7;      // 32 rows x 8 float4-chunks of the 32-col slice
        size_t src = (size_t)r * (KD * HH) + h * KD + q * 4;
        *(float4*)&swq[r * 68 + q * 4]        = *(const float4*)(Wq + src);
        *(float4*)&swkv[r * 68 + q * 4]       = *(const float4*)(Wk + src);
        *(float4*)&swkv[r * 68 + 32 + q * 4]  = *(const float4*)(Wv + src);
    }
    __syncthreads();

    // ---- KV projection: 128 rows x 64 cols (K|V), tile 8r x 4c per thread
    {
        const int rg = t & 15, cg = t >> 4;
        const int j0 = rg * 8, c0 = cg * 4;
        ull acc[8][2];
        #pragma unroll
        for (int r = 0; r < 8; r++) { acc[r][0] = 0ull; acc[r][1] = 0ull; }

        #pragma unroll 8
        for (int k = 0; k < KD; k++) {
            float4 a0 = *(const float4*)&sT[k * 132 + j0];
            float4 a1 = *(const float4*)&sT[k * 132 + j0 + 4];
            ulonglong2 b2 = *(const ulonglong2*)&swkv[k * 68 + c0];
            ull ad;
            ad = pack2(a0.x, a0.x); acc[0][0] = ffma2(ad, b2.x, acc[0][0]); acc[0][1] = ffma2(ad, b2.y, acc[0][1]);
            ad = pack2(a0.y, a0.y); acc[1][0] = ffma2(ad, b2.x, acc[1][0]); acc[1][1] = ffma2(ad, b2.y, acc[1][1]);
            ad = pack2(a0.z, a0.z); acc[2][0] = ffma2(ad, b2.x, acc[2][0]); acc[2][1] = ffma2(ad, b2.y, acc[2][1]);
            ad = pack2(a0.w, a0.w); acc[3][0] = ffma2(ad, b2.x, acc[3][0]); acc[3][1] = ffma2(ad, b2.y, acc[3][1]);
            ad = pack2(a1.x, a1.x); acc[4][0] = ffma2(ad, b2.x, acc[4][0]); acc[4][1] = ffma2(ad, b2.y, acc[4][1]);
            ad = pack2(a1.y, a1.y); acc[5][0] = ffma2(ad, b2.x, acc[5][0]); acc[5][1] = ffma2(ad, b2.y, acc[5][1]);
            ad = pack2(a1.z, a1.z); acc[6][0] = ffma2(ad, b2.x, acc[6][0]); acc[6][1] = ffma2(ad, b2.y, acc[6][1]);
            ad = pack2(a1.w, a1.w); acc[7][0] = ffma2(ad, b2.x, acc[7][0]); acc[7][1] = ffma2(ad, b2.y, acc[7][1]);
        }

        float cs[4][8];
        #pragma unroll
        for (int r = 0; r < 8; r++) {
            float2 e0 = unpack2(acc[r][0]), e1 = unpack2(acc[r][1]);
            cs[0][r] = e0.x; cs[1][r] = e0.y; cs[2][r] = e1.x; cs[3][r] = e1.y;
        }
        #pragma unroll
        for (int cc = 0; cc < 4; cc++) {
            int c = c0 + cc;
            float* dst = (c < KD) ? (kT + c * TT + j0) : (vT + (c - KD) * TT + j0);
            *(float4*)dst       = make_float4(cs[cc][0], cs[cc][1], cs[cc][2], cs[cc][3]);
            *(float4*)(dst + 4) = make_float4(cs[cc][4], cs[cc][5], cs[cc][6], cs[cc][7]);
        }
    }

    // ---- Q projection (threads 0-127); concat-tail copy (threads 128-255, h==0)
    if (t < 128) {
        const int rg = t & 15, cg = t >> 4;
        const int i0 = rg * 4, c0 = cg * 4;
        ull acc[4][2];
        #pragma unroll
        for (int r = 0; r < 4; r++) { acc[r][0] = 0ull; acc[r][1] = 0ull; }

        #pragma unroll 8
        for (int k = 0; k < KD; k++) {
            float4 a0 = *(const float4*)&sT[k * 132 + ig0 + i0];
            ulonglong2 b2 = *(const ulonglong2*)&swq[k * 68 + c0];
            ull ad;
            ad = pack2(a0.x, a0.x); acc[0][0] = ffma2(ad, b2.x, acc[0][0]); acc[0][1] = ffma2(ad, b2.y, acc[0][1]);
            ad = pack2(a0.y, a0.y); acc[1][0] = ffma2(ad, b2.x, acc[1][0]); acc[1][1] = ffma2(ad, b2.y, acc[1][1]);
            ad = pack2(a0.z, a0.z); acc[2][0] = ffma2(ad, b2.x, acc[2][0]); acc[2][1] = ffma2(ad, b2.y, acc[2][1]);
            ad = pack2(a0.w, a0.w); acc[3][0] = ffma2(ad, b2.x, acc[3][0]); acc[3][1] = ffma2(ad, b2.y, acc[3][1]);
        }
        float qs[4][4];
        #pragma unroll
        for (int r = 0; r < 4; r++) {
            float2 e0 = unpack2(acc[r][0]), e1 = unpack2(acc[r][1]);
            qs[0][r] = e0.x; qs[1][r] = e0.y; qs[2][r] = e1.x; qs[3][r] = e1.y;
        }
        #pragma unroll
        for (int cc = 0; cc < 4; cc++)
            *(float4*)&qT[(c0 + cc) * 64 + i0] =
                make_float4(qs[cc][0], qs[cc][1], qs[cc][2], qs[cc][3]);
    } else if (h == 0) {
        int n = t - 128;                           // 512 float4s, 4 per thread
        #pragma unroll
        for (int u = 0; u < 4; u++) {
            int m = n + u * 128;
            int row = m >> 3, c = (m & 7) * 4;
            size_t gr = (size_t)b * TT + ig0 + row;
            float4 v = *(const float4*)(state + gr * KD + c);
            *(float4*)(g_act + gr * DINP + 4 * KD + c) = v;
        }
    }
    __syncthreads();

    // ---- GEMM1: S^T[j][i] = K[j]·Q[i]; tile 8i x 4j (reads smem kT/qT)
    {
        const int ig = t >> 5, jg = t & 31;
        const int i0 = ig * 8, j0 = jg * 4;
        ull acc[4][4];
        #pragma unroll
        for (int c = 0; c < 4; c++)
            #pragma unroll
            for (int p = 0; p < 4; p++) acc[c][p] = 0ull;

        #pragma unroll 4
        for (int kk = 0; kk < KD; kk++) {
            const float* qrow = qT + kk * 64 + i0;
            ulonglong2 a01 = *(const ulonglong2*)qrow;
            ulonglong2 a23 = *(const ulonglong2*)(qrow + 4);
            float4 bj = *(const float4*)(kT + kk * TT + j0);
            ull bd;
            bd = pack2(bj.x, bj.x);
            acc[0][0] = ffma2(bd, a01.x, acc[0][0]); acc[0][1] = ffma2(bd, a01.y, acc[0][1]);
            acc[0][2] = ffma2(bd, a23.x, acc[0][2]); acc[0][3] = ffma2(bd, a23.y, acc[0][3]);
            bd = pack2(bj.y, bj.y);
            acc[1][0] = ffma2(bd, a01.x, acc[1][0]); acc[1][1] = ffma2(bd, a01.y, acc[1][1]);
            acc[1][2] = ffma2(bd, a23.x, acc[1][2]); acc[1][3] = ffma2(bd, a23.y, acc[1][3]);
            bd = pack2(bj.z, bj.z);
            acc[2][0] = ffma2(bd, a01.x, acc[2][0]); acc[2][1] = ffma2(bd, a01.y, acc[2][1]);
            acc[2][2] = ffma2(bd, a23.x, acc[2][2]); acc[2][3] = ffma2(bd, a23.y, acc[2][3]);
            bd = pack2(bj.w, bj.w);
            acc[3][0] = ffma2(bd, a01.x, acc[3][0]); acc[3][1] = ffma2(bd, a01.y, acc[3][1]);
            acc[3][2] = ffma2(bd, a23.x, acc[3][2]); acc[3][3] = ffma2(bd, a23.y, acc[3][3]);
        }

        __syncthreads();    // proj staging fully consumed before P overwrites it
        #pragma unroll
        for (int c = 0; c < 4; c++) {
            int jglob = j0 + c;
            int rd = jglob - ig0 - i0;          // diag position within my 8 i's
            if (rd >= 0 && rd < 8) {
                int p = rd >> 1, hi = rd & 1;
                float2 v = unpack2(acc[c][p]);
                if (hi) v.y = -1e30f; else v.x = -1e30f;
                acc[c][p] = pack2(v.x, v.y);
            }
            ull* dst = (ull*)&P[jglob * 64 + i0];
            dst[0] = acc[c][0]; dst[1] = acc[c][1];
            dst[2] = acc[c][2]; dst[3] = acc[c][3];
        }
    }
    __syncthreads();

    // ---- softmax (over j) on P, in place
    {
        const float scale = 0.17677669529663687f;   // 1/sqrt(32)
        const int i = t & 63, q = t >> 6;
        float mx = -1e30f;
        #pragma unroll 8
        for (int jj = 0; jj < 32; jj++)
            mx = fmaxf(mx, P[(q * 32 + jj) * 64 + i]);
        s_mx[q * 64 + i] = mx;
        __syncthreads();
        float m = fmaxf(fmaxf(s_mx[0 * 64 + i], s_mx[1 * 64 + i]),
                        fmaxf(s_mx[2 * 64 + i], s_mx[3 * 64 + i]));
        float sum = 0.f;
        #pragma unroll 8
        for (int jj = 0; jj < 32; jj++) {
            int idx = (q * 32 + jj) * 64 + i;
            float e = __expf((P[idx] - m) * scale);
            P[idx] = e;
            sum += e;
        }
        s_sm[q * 64 + i] = sum;
    }
    __syncthreads();
    if (t < 64)
        s_inv[t] = 1.f / (s_sm[0 * 64 + t] + s_sm[1 * 64 + t] +
                          s_sm[2 * 64 + t] + s_sm[3 * 64 + t]);
    __syncthreads();

    // ---- GEMM2: O[i][d] = sum_j P[j][i] * V[j][d]; tile 4i x 2d (smem vT)
    {
        const int ig = t & 15, dg = t >> 4;
        const int i0 = ig * 4, d0 = dg * 2;
        ull o[2][2];
        o[0][0] = 0ull; o[0][1] = 0ull; o[1][0] = 0ull; o[1][1] = 0ull;
        const float* v0p = vT + d0 * TT;
        const float* v1p = v0p + TT;

        for (int j = 0; j < TT; j += 4) {
            float4 v40 = *(const float4*)(v0p + j);
            float4 v41 = *(const float4*)(v1p + j);
            float va0[4] = {v40.x, v40.y, v40.z, v40.w};
            float va1[4] = {v41.x, v41.y, v41.z, v41.w};
            #pragma unroll
            for (int u = 0; u < 4; u++) {
                ulonglong2 a = *(const ulonglong2*)&P[(j + u) * 64 + i0];
                ull vd0 = pack2(va0[u], va0[u]);
                ull vd1 = pack2(va1[u], va1[u]);
                o[0][0] = ffma2(vd0, a.x, o[0][0]); o[0][1] = ffma2(vd0, a.y, o[0][1]);
                o[1][0] = ffma2(vd1, a.x, o[1][0]); o[1][1] = ffma2(vd1, a.y, o[1][1]);
            }
        }

        #pragma unroll
        for (int p = 0; p < 2; p++) {
            float2 e0 = unpack2(o[0][p]);
            float2 e1 = unpack2(o[1][p]);
            float r0[2] = {e0.x, e0.y};
            float r1[2] = {e1.x, e1.y};
            #pragma unroll
            for (int u = 0; u < 2; u++) {
                int il = i0 + p * 2 + u;
                int iglob = ig0 + il;
                float inv = s_inv[il];
                float out0 = r0[u] * inv - v0p[iglob];
                float out1 = r1[u] * inv - v1p[iglob];
                *(float2*)(g_act + ((size_t)b * TT + iglob) * DINP + h * KD + d0)
                    = make_float2(out0, out1);
            }
        }
    }
}

// ---------------------------------------------------------------------------
// Kernel 2 (fused MLP): 32 rows/block, grid 128 (single wave), 128 threads.
// Thread tile 8 rows x 8 cols: W smem reads amortized over 2x rows vs R5.
// h1 in smem only. W panels (8 k-rows) cp.async double-buffered.
// Dynamic smem: s_a 20KB + s_h1 32KB + s_w 16KB = 68KB.
// ---------------------------------------------------------------------------
#define CKP 8
#define MROWS 32
#define MLP_SMEM_BYTES ((MROWS * DINP + MROWS * HIDN + 2 * CKP * HIDN) * 4)

__global__ void __launch_bounds__(128, 1) mlp_kernel(
    const float* __restrict__ W1, const float* __restrict__ b1,
    const float* __restrict__ W2, const float* __restrict__ b2,
    const float* __restrict__ Wo, const float* __restrict__ bo,
    float* __restrict__ out)
{
    extern __shared__ float smf[];
    float* s_a  = smf;                           // [32][160]
    float* s_h1 = smf + MROWS * DINP;            // [32][256]
    float* s_w  = smf + MROWS * DINP + MROWS * HIDN;   // [2][8*256]

    const int rbase = blockIdx.x * MROWS;
    const int t = threadIdx.x;
    const int c0 = (t & 31) * 8;
    const int r0 = (t >> 5) * 8;                 // warp w -> rows 8w..8w+7
    const uint32_t wsm = (uint32_t)__cvta_generic_to_shared(s_w);

    // prologue: W1 panel 0 -> buf 0 (async), act tile -> smem (sync loads)
    #pragma unroll
    for (int u = 0; u < 4; u++)
        cpa16(wsm + (uint32_t)(t + u * 128) * 16, W1 + (size_t)(t + u * 128) * 4);
    cpa_commit();
    {
        const float4* src = (const float4*)(g_act + (size_t)rbase * DINP);
        float4* dst = (float4*)s_a;
        #pragma unroll
        for (int n = t; n < MROWS * DINP / 4; n += 128) dst[n] = src[n];
    }

    ull acc[8][4];
    {
        float4 bl = *(const float4*)(b1 + c0);
        float4 bh = *(const float4*)(b1 + c0 + 4);
        #pragma unroll
        for (int r = 0; r < 8; r++) {
            acc[r][0] = pack2(bl.x, bl.y); acc[r][1] = pack2(bl.z, bl.w);
            acc[r][2] = pack2(bh.x, bh.y); acc[r][3] = pack2(bh.z, bh.w);
        }
    }

    // ---- phase 1: k = 0..159 over W1
    const int NCH1 = DINP / CKP;   // 20
    for (int ch = 0; ch < NCH1; ch++) {
        if (ch + 1 < NCH1) {
            const uint32_t dstb = wsm + (uint32_t)(((ch + 1) & 1) * CKP * HIDN) * 4;
            const float* srcb = W1 + (size_t)(ch + 1) * CKP * HIDN;
            #pragma unroll
            for (int u = 0; u < 4; u++)
                cpa16(dstb + (uint32_t)(t + u * 128) * 16, srcb + (size_t)(t + u * 128) * 4);
            cpa_commit();
            cpa_wait<1>();
        } else {
            cpa_wait<0>();
        }
        __syncthreads();
        const float* wp = s_w + (ch & 1) * CKP * HIDN;
        const int kg0 = ch * CKP;
        #pragma unroll
        for (int kk = 0; kk < CKP; kk++) {
            ulonglong2 w01 = *(const ulonglong2*)(wp + kk * HIDN + c0);
            ulonglong2 w23 = *(const ulonglong2*)(wp + kk * HIDN + c0 + 4);
            #pragma unroll
            for (int r = 0; r < 8; r++) {
                float av = s_a[(r0 + r) * DINP + kg0 + kk];
                ull ad = pack2(av, av);
                acc[r][0] = ffma2(ad, w01.x, acc[r][0]);
                acc[r][1] = ffma2(ad, w01.y, acc[r][1]);
                acc[r][2] = ffma2(ad, w23.x, acc[r][2]);
                acc[r][3] = ffma2(ad, w23.y, acc[r][3]);
            }
        }
        __syncthreads();
    }

    // ---- relu -> s_h1, prefetch W2 panel 0
    #pragma unroll
    for (int u = 0; u < 4; u++)
        cpa16(wsm + (uint32_t)(t + u * 128) * 16, W2 + (size_t)(t + u * 128) * 4);
    cpa_commit();
    #pragma unroll
    for (int r = 0; r < 8; r++) {
        float2 p0 = unpack2(acc[r][0]), p1 = unpack2(acc[r][1]);
        float2 p2 = unpack2(acc[r][2]), p3 = unpack2(acc[r][3]);
        float* hrow = s_h1 + (r0 + r) * HIDN + c0;
        *(float4*)hrow = make_float4(fmaxf(p0.x, 0.f), fmaxf(p0.y, 0.f),
                                     fmaxf(p1.x, 0.f), fmaxf(p1.y, 0.f));
        *(float4*)(hrow + 4) = make_float4(fmaxf(p2.x, 0.f), fmaxf(p2.y, 0.f),
                                           fmaxf(p3.x, 0.f), fmaxf(p3.y, 0.f));
    }
    {
        float4 bl = *(const float4*)(b2 + c0);
        float4 bh = *(const float4*)(b2 + c0 + 4);
        #pragma unroll
        for (int r = 0; r < 8; r++) {
            acc[r][0] = pack2(bl.x, bl.y); acc[r][1] = pack2(bl.z, bl.w);
            acc[r][2] = pack2(bh.x, bh.y); acc[r][3] = pack2(bh.z, bh.w);
        }
    }
    __syncthreads();

    // ---- phase 2: k = 0..255 over W2, reading s_h1
    const int NCH2 = HIDN / CKP;   // 32
    for (int ch = 0; ch < NCH2; ch++) {
        if (ch + 1 < NCH2) {
            const uint32_t dstb = wsm + (uint32_t)(((ch + 1) & 1) * CKP * HIDN) * 4;
            const float* srcb = W2 + (size_t)(ch + 1) * CKP * HIDN;
            #pragma unroll
            for (int u = 0; u < 4; u++)
                cpa16(dstb + (uint32_t)(t + u * 128) * 16, srcb + (size_t)(t + u * 128) * 4);
            cpa_commit();
            cpa_wait<1>();
        } else {
            cpa_wait<0>();
        }
        __syncthreads();
        const float* wp = s_w + (ch & 1) * CKP * HIDN;
        const int kg0 = ch * CKP;
        #pragma unroll
        for (int kk = 0; kk < CKP; kk++) {
            ulonglong2 w01 = *(const ulonglong2*)(wp + kk * HIDN + c0);
            ulonglong2 w23 = *(const ulonglong2*)(wp + kk * HIDN + c0 + 4);
            #pragma unroll
            for (int r = 0; r < 8; r++) {
                float av = s_h1[(r0 + r) * HIDN + kg0 + kk];
                ull ad = pack2(av, av);
                acc[r][0] = ffma2(ad, w01.x, acc[r][0]);
                acc[r][1] = ffma2(ad, w01.y, acc[r][1]);
                acc[r][2] = ffma2(ad, w23.x, acc[r][2]);
                acc[r][3] = ffma2(ad, w23.y, acc[r][3]);
            }
        }
        __syncthreads();
    }

    // ---- relu + dot with Wo slice; warp spans all 256 cols -> pure shfl
    float4 wl = *(const float4*)(Wo + c0);
    float4 wh = *(const float4*)(Wo + c0 + 4);
    float p[8];
    #pragma unroll
    for (int r = 0; r < 8; r++) {
        float2 p0 = unpack2(acc[r][0]), p1 = unpack2(acc[r][1]);
        float2 p2 = unpack2(acc[r][2]), p3 = unpack2(acc[r][3]);
        float s = 0.f;
        s = fmaf(fmaxf(p0.x, 0.f), wl.x, s);
        s = fmaf(fmaxf(p0.y, 0.f), wl.y, s);
        s = fmaf(fmaxf(p1.x, 0.f), wl.z, s);
        s = fmaf(fmaxf(p1.y, 0.f), wl.w, s);
        s = fmaf(fmaxf(p2.x, 0.f), wh.x, s);
        s = fmaf(fmaxf(p2.y, 0.f), wh.y, s);
        s = fmaf(fmaxf(p3.x, 0.f), wh.z, s);
        s = fmaf(fmaxf(p3.y, 0.f), wh.w, s);
        p[r] = s;
    }
    #pragma unroll
    for (int off = 16; off; off >>= 1) {
        #pragma unroll
        for (int r = 0; r < 8; r++)
            p[r] += __shfl_down_sync(0xffffffffu, p[r], off);
    }
    if ((t & 31) == 0) {
        float bv = bo[0];
        #pragma unroll
        for (int r = 0; r < 8; r++)
            out[rbase + r0 + r] = p[r] + bv;
    }
}

// ---------------------------------------------------------------------------
extern "C" void kernel_launch(void* const* d_in, const int* in_sizes, int n_in,
                              void* d_out, int out_size)
{
    (void)in_sizes; (void)n_in; (void)out_size;
    const float* state = (const float*)d_in[0];
    const float* Wq    = (const float*)d_in[1];
    const float* Wk    = (const float*)d_in[2];
    const float* Wv    = (const float*)d_in[3];
    const float* W1    = (const float*)d_in[4];
    const float* b1    = (const float*)d_in[5];
    const float* W2    = (const float*)d_in[6];
    const float* b2    = (const float*)d_in[7];
    const float* Wo    = (const float*)d_in[8];
    const float* bo    = (const float*)d_in[9];
    float* out = (float*)d_out;

    cudaFuncSetAttribute(attn_kernel,
                         cudaFuncAttributeMaxDynamicSharedMemorySize,
                         ATTN_SMEM_BYTES);
    cudaFuncSetAttribute(mlp_kernel,
                         cudaFuncAttributeMaxDynamicSharedMemorySize,
                         MLP_SMEM_BYTES);
    attn_kernel<<<BB * HH * 2, 256, ATTN_SMEM_BYTES>>>(state, Wq, Wk, Wv);
    mlp_kernel<<<(BB * TT) / MROWS, 128, MLP_SMEM_BYTES>>>(W1, b1, W2, b2, Wo, bo, out);
}

// round 10
// speedup vs baseline: 1.7195x; 1.0279x over previous
#include <cuda_runtime.h>
#include <cstdint>

#define BB   32
#define TT   128
#define KD   32
#define HH   4
#define DINP 160
#define HIDN 256

// Scratch (static device global; no allocation).
__device__ float g_act[BB * TT * DINP];     // [x | state]  4096 x 160

typedef unsigned long long ull;

__device__ __forceinline__ ull ffma2(ull a, ull b, ull c) {
    ull d;
    asm("fma.rn.f32x2 %0, %1, %2, %3;" : "=l"(d) : "l"(a), "l"(b), "l"(c));
    return d;
}
__device__ __forceinline__ ull pack2(float x, float y) {
    ull r;
    asm("mov.b64 %0, {%1, %2};" : "=l"(r) : "f"(x), "f"(y));
    return r;
}
__device__ __forceinline__ float2 unpack2(ull v) {
    float x, y;
    asm("mov.b64 {%0, %1}, %2;" : "=f"(x), "=f"(y) : "l"(v));
    return make_float2(x, y);
}
__device__ __forceinline__ void cpa16(uint32_t dst_smem, const void* src) {
    asm volatile("cp.async.cg.shared.global [%0], [%1], 16;\n"
                 :: "r"(dst_smem), "l"(src) : "memory");
}
__device__ __forceinline__ void cpa_commit() {
    asm volatile("cp.async.commit_group;\n" ::: "memory");
}
template <int N>
__device__ __forceinline__ void cpa_wait() {
    asm volatile("cp.async.wait_group %0;\n" :: "n"(N) : "memory");
}

// ---------------------------------------------------------------------------
// Fused attention smem layout (floats). P aliases the proj staging region.
// ---------------------------------------------------------------------------
#define OFF_ST    0            // stateT [32][pitch 132]       4224
#define OFF_WQ    4224         // WqT-slice [32][pitch 68]     2176
#define OFF_WKV   6400         // Wk|Wv slice [32][pitch 68]   2176  (end 8576)
#define OFF_P     0            // P [128][64]                  8192  (alias)
#define OFF_KT    8576         // kT [32][128]                 4096
#define OFF_VT    12672        // vT [32][128]                 4096
#define OFF_QT    16768        // qT [32][64]                  2048
#define OFF_MX    18816        // [4][64]
#define OFF_SM    19072        // [4][64]
#define OFF_INV   19328        // [64]
#define ATTN_SMEM_FLOATS 19392
#define ATTN_SMEM_BYTES  (ATTN_SMEM_FLOATS * 4)

// ---------------------------------------------------------------------------
// Kernel 1 (fused QKV-proj + masked attention), 64 query rows of one (b,h).
// grid 256 = (b, h, ihalf), 256 threads, 2 CTA/SM.  (identical to R8/R9)
// ---------------------------------------------------------------------------
__global__ void __launch_bounds__(256, 2) attn_kernel(
    const float* __restrict__ state,
    const float* __restrict__ Wq,
    const float* __restrict__ Wk,
    const float* __restrict__ Wv)
{
    extern __shared__ float sm[];
    const int bx = blockIdx.x;
    const int b = bx >> 3, h = (bx >> 1) & 3, ihalf = bx & 1;
    const int t = threadIdx.x;
    const int ig0 = ihalf * 64;

    float* sT    = sm + OFF_ST;
    float* swq   = sm + OFF_WQ;
    float* swkv  = sm + OFF_WKV;
    float* P     = sm + OFF_P;
    float* kT    = sm + OFF_KT;
    float* vT    = sm + OFF_VT;
    float* qT    = sm + OFF_QT;
    float* s_mx  = sm + OFF_MX;
    float* s_sm  = sm + OFF_SM;
    float* s_inv = sm + OFF_INV;

    // ---- stage stateT [c][j] (pitch 132) and weight slices (pitch 68)
    {
        int r = t >> 1, c0 = (t & 1) * 16;
        const float4* p = (const float4*)(state + ((size_t)b * TT + r) * KD + c0);
        #pragma unroll
        for (int w = 0; w < 4; w++) {
            float4 v = p[w];
            sT[(c0 + 4 * w + 0) * 132 + r] = v.x;
            sT[(c0 + 4 * w + 1) * 132 + r] = v.y;
            sT[(c0 + 4 * w + 2) * 132 + r] = v.z;
            sT[(c0 + 4 * w + 3) * 132 + r] = v.w;
        }
    }
    {
        int r = t >> 3, q = t & 7;      // 32 rows x 8 float4-chunks of the 32-col slice
        size_t src = (size_t)r * (KD * HH) + h * KD + q * 4;
        *(float4*)&swq[r * 68 + q * 4]        = *(const float4*)(Wq + src);
        *(float4*)&swkv[r * 68 + q * 4]       = *(const float4*)(Wk + src);
        *(float4*)&swkv[r * 68 + 32 + q * 4]  = *(const float4*)(Wv + src);
    }
    __syncthreads();

    // ---- KV projection: 128 rows x 64 cols (K|V), tile 8r x 4c per thread
    {
        const int rg = t & 15, cg = t >> 4;
        const int j0 = rg * 8, c0 = cg * 4;
        ull acc[8][2];
        #pragma unroll
        for (int r = 0; r < 8; r++) { acc[r][0] = 0ull; acc[r][1] = 0ull; }

        #pragma unroll 8
        for (int k = 0; k < KD; k++) {
            float4 a0 = *(const float4*)&sT[k * 132 + j0];
            float4 a1 = *(const float4*)&sT[k * 132 + j0 + 4];
            ulonglong2 b2 = *(const ulonglong2*)&swkv[k * 68 + c0];
            ull ad;
            ad = pack2(a0.x, a0.x); acc[0][0] = ffma2(ad, b2.x, acc[0][0]); acc[0][1] = ffma2(ad, b2.y, acc[0][1]);
            ad = pack2(a0.y, a0.y); acc[1][0] = ffma2(ad, b2.x, acc[1][0]); acc[1][1] = ffma2(ad, b2.y, acc[1][1]);
            ad = pack2(a0.z, a0.z); acc[2][0] = ffma2(ad, b2.x, acc[2][0]); acc[2][1] = ffma2(ad, b2.y, acc[2][1]);
            ad = pack2(a0.w, a0.w); acc[3][0] = ffma2(ad, b2.x, acc[3][0]); acc[3][1] = ffma2(ad, b2.y, acc[3][1]);
            ad = pack2(a1.x, a1.x); acc[4][0] = ffma2(ad, b2.x, acc[4][0]); acc[4][1] = ffma2(ad, b2.y, acc[4][1]);
            ad = pack2(a1.y, a1.y); acc[5][0] = ffma2(ad, b2.x, acc[5][0]); acc[5][1] = ffma2(ad, b2.y, acc[5][1]);
            ad = pack2(a1.z, a1.z); acc[6][0] = ffma2(ad, b2.x, acc[6][0]); acc[6][1] = ffma2(ad, b2.y, acc[6][1]);
            ad = pack2(a1.w, a1.w); acc[7][0] = ffma2(ad, b2.x, acc[7][0]); acc[7][1] = ffma2(ad, b2.y, acc[7][1]);
        }

        float cs[4][8];
        #pragma unroll
        for (int r = 0; r < 8; r++) {
            float2 e0 = unpack2(acc[r][0]), e1 = unpack2(acc[r][1]);
            cs[0][r] = e0.x; cs[1][r] = e0.y; cs[2][r] = e1.x; cs[3][r] = e1.y;
        }
        #pragma unroll
        for (int cc = 0; cc < 4; cc++) {
            int c = c0 + cc;
            float* dst = (c < KD) ? (kT + c * TT + j0) : (vT + (c - KD) * TT + j0);
            *(float4*)dst       = make_float4(cs[cc][0], cs[cc][1], cs[cc][2], cs[cc][3]);
            *(float4*)(dst + 4) = make_float4(cs[cc][4], cs[cc][5], cs[cc][6], cs[cc][7]);
        }
    }

    // ---- Q projection (threads 0-127); concat-tail copy (threads 128-255, h==0)
    if (t < 128) {
        const int rg = t & 15, cg = t >> 4;
        const int i0 = rg * 4, c0 = cg * 4;
        ull acc[4][2];
        #pragma unroll
        for (int r = 0; r < 4; r++) { acc[r][0] = 0ull; acc[r][1] = 0ull; }

        #pragma unroll 8
        for (int k = 0; k < KD; k++) {
            float4 a0 = *(const float4*)&sT[k * 132 + ig0 + i0];
            ulonglong2 b2 = *(const ulonglong2*)&swq[k * 68 + c0];
            ull ad;
            ad = pack2(a0.x, a0.x); acc[0][0] = ffma2(ad, b2.x, acc[0][0]); acc[0][1] = ffma2(ad, b2.y, acc[0][1]);
            ad = pack2(a0.y, a0.y); acc[1][0] = ffma2(ad, b2.x, acc[1][0]); acc[1][1] = ffma2(ad, b2.y, acc[1][1]);
            ad = pack2(a0.z, a0.z); acc[2][0] = ffma2(ad, b2.x, acc[2][0]); acc[2][1] = ffma2(ad, b2.y, acc[2][1]);
            ad = pack2(a0.w, a0.w); acc[3][0] = ffma2(ad, b2.x, acc[3][0]); acc[3][1] = ffma2(ad, b2.y, acc[3][1]);
        }
        float qs[4][4];
        #pragma unroll
        for (int r = 0; r < 4; r++) {
            float2 e0 = unpack2(acc[r][0]), e1 = unpack2(acc[r][1]);
            qs[0][r] = e0.x; qs[1][r] = e0.y; qs[2][r] = e1.x; qs[3][r] = e1.y;
        }
        #pragma unroll
        for (int cc = 0; cc < 4; cc++)
            *(float4*)&qT[(c0 + cc) * 64 + i0] =
                make_float4(qs[cc][0], qs[cc][1], qs[cc][2], qs[cc][3]);
    } else if (h == 0) {
        int n = t - 128;                           // 512 float4s, 4 per thread
        #pragma unroll
        for (int u = 0; u < 4; u++) {
            int m = n + u * 128;
            int row = m >> 3, c = (m & 7) * 4;
            size_t gr = (size_t)b * TT + ig0 + row;
            float4 v = *(const float4*)(state + gr * KD + c);
            *(float4*)(g_act + gr * DINP + 4 * KD + c) = v;
        }
    }
    __syncthreads();

    // ---- GEMM1: S^T[j][i] = K[j]·Q[i]; tile 8i x 4j (reads smem kT/qT)
    {
        const int ig = t >> 5, jg = t & 31;
        const int i0 = ig * 8, j0 = jg * 4;
        ull acc[4][4];
        #pragma unroll
        for (int c = 0; c < 4; c++)
            #pragma unroll
            for (int p = 0; p < 4; p++) acc[c][p] = 0ull;

        #pragma unroll 4
        for (int kk = 0; kk < KD; kk++) {
            const float* qrow = qT + kk * 64 + i0;
            ulonglong2 a01 = *(const ulonglong2*)qrow;
            ulonglong2 a23 = *(const ulonglong2*)(qrow + 4);
            float4 bj = *(const float4*)(kT + kk * TT + j0);
            ull bd;
            bd = pack2(bj.x, bj.x);
            acc[0][0] = ffma2(bd, a01.x, acc[0][0]); acc[0][1] = ffma2(bd, a01.y, acc[0][1]);
            acc[0][2] = ffma2(bd, a23.x, acc[0][2]); acc[0][3] = ffma2(bd, a23.y, acc[0][3]);
            bd = pack2(bj.y, bj.y);
            acc[1][0] = ffma2(bd, a01.x, acc[1][0]); acc[1][1] = ffma2(bd, a01.y, acc[1][1]);
            acc[1][2] = ffma2(bd, a23.x, acc[1][2]); acc[1][3] = ffma2(bd, a23.y, acc[1][3]);
            bd = pack2(bj.z, bj.z);
            acc[2][0] = ffma2(bd, a01.x, acc[2][0]); acc[2][1] = ffma2(bd, a01.y, acc[2][1]);
            acc[2][2] = ffma2(bd, a23.x, acc[2][2]); acc[2][3] = ffma2(bd, a23.y, acc[2][3]);
            bd = pack2(bj.w, bj.w);
            acc[3][0] = ffma2(bd, a01.x, acc[3][0]); acc[3][1] = ffma2(bd, a01.y, acc[3][1]);
            acc[3][2] = ffma2(bd, a23.x, acc[3][2]); acc[3][3] = ffma2(bd, a23.y, acc[3][3]);
        }

        __syncthreads();    // proj staging fully consumed before P overwrites it
        #pragma unroll
        for (int c = 0; c < 4; c++) {
            int jglob = j0 + c;
            int rd = jglob - ig0 - i0;          // diag position within my 8 i's
            if (rd >= 0 && rd < 8) {
                int p = rd >> 1, hi = rd & 1;
                float2 v = unpack2(acc[c][p]);
                if (hi) v.y = -1e30f; else v.x = -1e30f;
                acc[c][p] = pack2(v.x, v.y);
            }
            ull* dst = (ull*)&P[jglob * 64 + i0];
            dst[0] = acc[c][0]; dst[1] = acc[c][1];
            dst[2] = acc[c][2]; dst[3] = acc[c][3];
        }
    }
    __syncthreads();

    // ---- softmax (over j) on P, in place
    {
        const float scale = 0.17677669529663687f;   // 1/sqrt(32)
        const int i = t & 63, q = t >> 6;
        float mx = -1e30f;
        #pragma unroll 8
        for (int jj = 0; jj < 32; jj++)
            mx = fmaxf(mx, P[(q * 32 + jj) * 64 + i]);
        s_mx[q * 64 + i] = mx;
        __syncthreads();
        float m = fmaxf(fmaxf(s_mx[0 * 64 + i], s_mx[1 * 64 + i]),
                        fmaxf(s_mx[2 * 64 + i], s_mx[3 * 64 + i]));
        float sum = 0.f;
        #pragma unroll 8
        for (int jj = 0; jj < 32; jj++) {
            int idx = (q * 32 + jj) * 64 + i;
            float e = __expf((P[idx] - m) * scale);
            P[idx] = e;
            sum += e;
        }
        s_sm[q * 64 + i] = sum;
    }
    __syncthreads();
    if (t < 64)
        s_inv[t] = 1.f / (s_sm[0 * 64 + t] + s_sm[1 * 64 + t] +
                          s_sm[2 * 64 + t] + s_sm[3 * 64 + t]);
    __syncthreads();

    // ---- GEMM2: O[i][d] = sum_j P[j][i] * V[j][d]; tile 4i x 2d (smem vT)
    {
        const int ig = t & 15, dg = t >> 4;
        const int i0 = ig * 4, d0 = dg * 2;
        ull o[2][2];
        o[0][0] = 0ull; o[0][1] = 0ull; o[1][0] = 0ull; o[1][1] = 0ull;
        const float* v0p = vT + d0 * TT;
        const float* v1p = v0p + TT;

        for (int j = 0; j < TT; j += 4) {
            float4 v40 = *(const float4*)(v0p + j);
            float4 v41 = *(const float4*)(v1p + j);
            float va0[4] = {v40.x, v40.y, v40.z, v40.w};
            float va1[4] = {v41.x, v41.y, v41.z, v41.w};
            #pragma unroll
            for (int u = 0; u < 4; u++) {
                ulonglong2 a = *(const ulonglong2*)&P[(j + u) * 64 + i0];
                ull vd0 = pack2(va0[u], va0[u]);
                ull vd1 = pack2(va1[u], va1[u]);
                o[0][0] = ffma2(vd0, a.x, o[0][0]); o[0][1] = ffma2(vd0, a.y, o[0][1]);
                o[1][0] = ffma2(vd1, a.x, o[1][0]); o[1][1] = ffma2(vd1, a.y, o[1][1]);
            }
        }

        #pragma unroll
        for (int p = 0; p < 2; p++) {
            float2 e0 = unpack2(o[0][p]);
            float2 e1 = unpack2(o[1][p]);
            float r0[2] = {e0.x, e0.y};
            float r1[2] = {e1.x, e1.y};
            #pragma unroll
            for (int u = 0; u < 2; u++) {
                int il = i0 + p * 2 + u;
                int iglob = ig0 + il;
                float inv = s_inv[il];
                float out0 = r0[u] * inv - v0p[iglob];
                float out1 = r1[u] * inv - v1p[iglob];
                *(float2*)(g_act + ((size_t)b * TT + iglob) * DINP + h * KD + d0)
                    = make_float2(out0, out1);
            }
        }
    }
}

// ---------------------------------------------------------------------------
// Kernel 2 (fused MLP): 32 rows/block, grid 128 (single wave), 256 threads.
// Warp w = (colhalf w&1, rowgroup w>>1): tile 8 rows x 4 cols over a 128-col
// half. W LDS.128 traffic unchanged vs R9 (each warp reads half the row);
// a loaded as float4 broadcasts (4 k per LDS). 8 warps/SM hide LDS latency.
// Dynamic smem: s_a 20KB + s_h1 32KB + s_w 16KB = 68KB.
// ---------------------------------------------------------------------------
#define CKP 8
#define MROWS 32
#define MLP_SMEM_BYTES ((MROWS * DINP + MROWS * HIDN + 2 * CKP * HIDN) * 4)

__global__ void __launch_bounds__(256, 1) mlp_kernel(
    const float* __restrict__ W1, const float* __restrict__ b1,
    const float* __restrict__ W2, const float* __restrict__ b2,
    const float* __restrict__ Wo, const float* __restrict__ bo,
    float* __restrict__ out)
{
    extern __shared__ float smf[];
    float* s_a  = smf;                                  // [32][160]
    float* s_h1 = smf + MROWS * DINP;                   // [32][256]
    float* s_w  = smf + MROWS * DINP + MROWS * HIDN;    // [2][8*256]
    __shared__ float s_red[MROWS][2];

    const int rbase = blockIdx.x * MROWS;
    const int t = threadIdx.x;
    const int wrp  = t >> 5;
    const int lane = t & 31;
    const int c0 = (wrp & 1) * 128 + lane * 4;          // 4 cols in my 128-col half
    const int r0 = (wrp >> 1) * 8;                      // 8 rows
    const uint32_t wsm = (uint32_t)__cvta_generic_to_shared(s_w);

    // prologue: W1 panel 0 -> buf 0 (async), act tile -> smem (sync loads)
    #pragma unroll
    for (int u = 0; u < 2; u++)
        cpa16(wsm + (uint32_t)(t + u * 256) * 16, W1 + (size_t)(t + u * 256) * 4);
    cpa_commit();
    {
        const float4* src = (const float4*)(g_act + (size_t)rbase * DINP);
        float4* dst = (float4*)s_a;
        #pragma unroll
        for (int n = t; n < MROWS * DINP / 4; n += 256) dst[n] = src[n];
    }

    ull acc[8][2];
    {
        float4 bl = *(const float4*)(b1 + c0);
        #pragma unroll
        for (int r = 0; r < 8; r++) {
            acc[r][0] = pack2(bl.x, bl.y);
            acc[r][1] = pack2(bl.z, bl.w);
        }
    }

    // ---- phase 1: k = 0..159 over W1
    const int NCH1 = DINP / CKP;   // 20
    for (int ch = 0; ch < NCH1; ch++) {
        if (ch + 1 < NCH1) {
            const uint32_t dstb = wsm + (uint32_t)(((ch + 1) & 1) * CKP * HIDN) * 4;
            const float* srcb = W1 + (size_t)(ch + 1) * CKP * HIDN;
            #pragma unroll
            for (int u = 0; u < 2; u++)
                cpa16(dstb + (uint32_t)(t + u * 256) * 16, srcb + (size_t)(t + u * 256) * 4);
            cpa_commit();
            cpa_wait<1>();
        } else {
            cpa_wait<0>();
        }
        __syncthreads();
        const float* wp = s_w + (ch & 1) * CKP * HIDN;
        const int kg0 = ch * CKP;
        #pragma unroll
        for (int half = 0; half < 2; half++) {
            float4 areg[8];                       // 8 rows x 4 k (broadcast LDS.128)
            #pragma unroll
            for (int r = 0; r < 8; r++)
                areg[r] = *(const float4*)&s_a[(r0 + r) * DINP + kg0 + half * 4];
            #pragma unroll
            for (int k2 = 0; k2 < 4; k2++) {
                ulonglong2 w01 = *(const ulonglong2*)(wp + (half * 4 + k2) * HIDN + c0);
                #pragma unroll
                for (int r = 0; r < 8; r++) {
                    float av = (k2 == 0) ? areg[r].x : (k2 == 1) ? areg[r].y
                             : (k2 == 2) ? areg[r].z : areg[r].w;
                    ull ad = pack2(av, av);
                    acc[r][0] = ffma2(ad, w01.x, acc[r][0]);
                    acc[r][1] = ffma2(ad, w01.y, acc[r][1]);
                }
            }
        }
        __syncthreads();
    }

    // ---- relu -> s_h1, prefetch W2 panel 0
    #pragma unroll
    for (int u = 0; u < 2; u++)
        cpa16(wsm + (uint32_t)(t + u * 256) * 16, W2 + (size_t)(t + u * 256) * 4);
    cpa_commit();
    #pragma unroll
    for (int r = 0; r < 8; r++) {
        float2 p0 = unpack2(acc[r][0]), p1 = unpack2(acc[r][1]);
        *(float4*)&s_h1[(r0 + r) * HIDN + c0] =
            make_float4(fmaxf(p0.x, 0.f), fmaxf(p0.y, 0.f),
                        fmaxf(p1.x, 0.f), fmaxf(p1.y, 0.f));
    }
    {
        float4 bl = *(const float4*)(b2 + c0);
        #pragma unroll
        for (int r = 0; r < 8; r++) {
            acc[r][0] = pack2(bl.x, bl.y);
            acc[r][1] = pack2(bl.z, bl.w);
        }
    }
    __syncthreads();

    // ---- phase 2: k = 0..255 over W2, reading s_h1
    const int NCH2 = HIDN / CKP;   // 32
    for (int ch = 0; ch < NCH2; ch++) {
        if (ch + 1 < NCH2) {
            const uint32_t dstb = wsm + (uint32_t)(((ch + 1) & 1) * CKP * HIDN) * 4;
            const float* srcb = W2 + (size_t)(ch + 1) * CKP * HIDN;
            #pragma unroll
            for (int u = 0; u < 2; u++)
                cpa16(dstb + (uint32_t)(t + u * 256) * 16, srcb + (size_t)(t + u * 256) * 4);
            cpa_commit();
            cpa_wait<1>();
        } else {
            cpa_wait<0>();
        }
        __syncthreads();
        const float* wp = s_w + (ch & 1) * CKP * HIDN;
        const int kg0 = ch * CKP;
        #pragma unroll
        for (int half = 0; half < 2; half++) {
            float4 areg[8];
            #pragma unroll
            for (int r = 0; r < 8; r++)
                areg[r] = *(const float4*)&s_h1[(r0 + r) * HIDN + kg0 + half * 4];
            #pragma unroll
            for (int k2 = 0; k2 < 4; k2++) {
                ulonglong2 w01 = *(const ulonglong2*)(wp + (half * 4 + k2) * HIDN + c0);
                #pragma unroll
                for (int r = 0; r < 8; r++) {
                    float av = (k2 == 0) ? areg[r].x : (k2 == 1) ? areg[r].y
                             : (k2 == 2) ? areg[r].z : areg[r].w;
                    ull ad = pack2(av, av);
                    acc[r][0] = ffma2(ad, w01.x, acc[r][0]);
                    acc[r][1] = ffma2(ad, w01.y, acc[r][1]);
                }
            }
        }
        __syncthreads();
    }

    // ---- relu + dot with my 4-col Wo slice; full-warp shfl covers 128 cols,
    //      then combine the two column-halves via s_red.
    float4 wl = *(const float4*)(Wo + c0);
    float p[8];
    #pragma unroll
    for (int r = 0; r < 8; r++) {
        float2 p0 = unpack2(acc[r][0]), p1 = unpack2(acc[r][1]);
        float s = 0.f;
        s = fmaf(fmaxf(p0.x, 0.f), wl.x, s);
        s = fmaf(fmaxf(p0.y, 0.f), wl.y, s);
        s = fmaf(fmaxf(p1.x, 0.f), wl.z, s);
        s = fmaf(fmaxf(p1.y, 0.f), wl.w, s);
        p[r] = s;
    }
    #pragma unroll
    for (int off = 16; off; off >>= 1) {
        #pragma unroll
        for (int r = 0; r < 8; r++)
            p[r] += __shfl_down_sync(0xffffffffu, p[r], off);
    }
    if (lane == 0) {
        #pragma unroll
        for (int r = 0; r < 8; r++)
            s_red[r0 + r][wrp & 1] = p[r];
    }
    __syncthreads();
    if (t < MROWS)
        out[rbase + t] = s_red[t][0] + s_red[t][1] + bo[0];
}

// ---------------------------------------------------------------------------
extern "C" void kernel_launch(void* const* d_in, const int* in_sizes, int n_in,
                              void* d_out, int out_size)
{
    (void)in_sizes; (void)n_in; (void)out_size;
    const float* state = (const float*)d_in[0];
    const float* Wq    = (const float*)d_in[1];
    const float* Wk    = (const float*)d_in[2];
    const float* Wv    = (const float*)d_in[3];
    const float* W1    = (const float*)d_in[4];
    const float* b1    = (const float*)d_in[5];
    const float* W2    = (const float*)d_in[6];
    const float* b2    = (const float*)d_in[7];
    const float* Wo    = (const float*)d_in[8];
    const float* bo    = (const float*)d_in[9];
    float* out = (float*)d_out;

    cudaFuncSetAttribute(attn_kernel,
                         cudaFuncAttributeMaxDynamicSharedMemorySize,
                         ATTN_SMEM_BYTES);
    cudaFuncSetAttribute(mlp_kernel,
                         cudaFuncAttributeMaxDynamicSharedMemorySize,
                         MLP_SMEM_BYTES);
    attn_kernel<<<BB * HH * 2, 256, ATTN_SMEM_BYTES>>>(state, Wq, Wk, Wv);
    mlp_kernel<<<(BB * TT) / MROWS, 256, MLP_SMEM_BYTES>>>(W1, b1, W2, b2, Wo, bo, out);
}